// round 3
// baseline (speedup 1.0000x reference)
#include <cuda_runtime.h>
#include <math.h>
#include <stdint.h>

// Problem constants (fixed shapes)
#define B_  16
#define T_  1000
#define TT_ 2000
#define F_  512
#define H_  512
#define HH_ 1024

// ---------------- device scratch ----------------
__device__ float g_wzh [B_ * TT_ * HH_];   // BN'd pre-activations
__device__ float g_hseq[B_ * TT_ * H_ ];   // hidden states over the 2000-step scan
__device__ float g_ln  [B_ * T_  * HH_];   // layernorm output
__device__ float g_scale[HH_];
__device__ float g_bias [HH_];
__device__ unsigned int g_flag[8 * 16 * 32];  // per-(group,CTA) epoch flags, 128B apart

// ---------------- packed fp32x2 FMA ----------------
__device__ __forceinline__ float2 ffma2(float2 a, float2 b, float2 c) {
    float2 d;
    asm("fma.rn.f32x2 %0, %1, %2, %3;"
        : "=l"(reinterpret_cast<unsigned long long &>(d))
        : "l"(reinterpret_cast<unsigned long long &>(a)),
          "l"(reinterpret_cast<unsigned long long &>(b)),
          "l"(reinterpret_cast<unsigned long long &>(c)));
    return d;
}

__device__ __forceinline__ uint32_t smem_u32(const void* p) {
    uint32_t a;
    asm("{ .reg .u64 t; cvta.to.shared.u64 t, %1; cvt.u32.u64 %0, t; }" : "=r"(a) : "l"(p));
    return a;
}

// ---------------- prep ----------------
__global__ void prep_kernel(const float* __restrict__ bz, const float* __restrict__ bh,
                            const float* __restrict__ zg, const float* __restrict__ zb,
                            const float* __restrict__ zm, const float* __restrict__ zv,
                            const float* __restrict__ hg, const float* __restrict__ hb,
                            const float* __restrict__ hm, const float* __restrict__ hv) {
    int n = threadIdx.x;  // 1024 threads
    float sc, bi;
    if (n < 512) {
        sc = zg[n] * rsqrtf(zv[n] + 1e-5f);
        bi = (bz[n] - zm[n]) * sc + zb[n];
    } else {
        int j = n - 512;
        sc = hg[j] * rsqrtf(hv[j] + 1e-5f);
        bi = (bh[j] - hm[j]) * sc + hb[j];
    }
    g_scale[n] = sc;
    g_bias[n]  = bi;
    for (int i = n; i < 8 * 16 * 32; i += 1024) g_flag[i] = 0u;
}

// ---------------- phase 1: wzh = BN(x_cat @ [Wz;Wh]^T + b) ----------------
__global__ __launch_bounds__(256) void gemm_wzh(const float* __restrict__ x,
                                                const float* __restrict__ Wz,
                                                const float* __restrict__ Wh) {
    __shared__ __align__(16) float As[32][68];
    __shared__ __align__(16) float Bs[32][68];
    int tid = threadIdx.x;
    int tx = tid & 15, ty = tid >> 4;
    int m0 = blockIdx.y * 64, n0 = blockIdx.x * 64;

    float2 acc[4][2];
#pragma unroll
    for (int i = 0; i < 4; i++) { acc[i][0] = make_float2(0.f, 0.f); acc[i][1] = make_float2(0.f, 0.f); }

    for (int k0 = 0; k0 < 512; k0 += 32) {
#pragma unroll
        for (int u = 0; u < 2; u++) {
            int v  = tid * 2 + u;
            int mm = v >> 3;
            int k4 = (v & 7) * 4;

            int m = m0 + mm;
            int b = m / TT_;
            int tp = m - b * TT_;
            const float* arow = (tp < T_) ? (x + ((size_t)(b * T_ + tp) << 9))
                                          : (x + ((size_t)((15 - b) * T_ + (tp - T_)) << 9));
            float4 av = *(const float4*)(arow + k0 + k4);
            As[k4 + 0][mm] = av.x; As[k4 + 1][mm] = av.y; As[k4 + 2][mm] = av.z; As[k4 + 3][mm] = av.w;

            int n = n0 + mm;
            const float* brow = (n < 512) ? (Wz + ((size_t)n << 9))
                                          : (Wh + ((size_t)(n - 512) << 9));
            float4 bv = *(const float4*)(brow + k0 + k4);
            Bs[k4 + 0][mm] = bv.x; Bs[k4 + 1][mm] = bv.y; Bs[k4 + 2][mm] = bv.z; Bs[k4 + 3][mm] = bv.w;
        }
        __syncthreads();
#pragma unroll
        for (int k = 0; k < 32; k++) {
            float4 a4 = *(const float4*)&As[k][ty * 4];
            float4 b4 = *(const float4*)&Bs[k][tx * 4];
            float2 b20 = make_float2(b4.x, b4.y), b21 = make_float2(b4.z, b4.w);
            float av[4] = {a4.x, a4.y, a4.z, a4.w};
#pragma unroll
            for (int i = 0; i < 4; i++) {
                float2 ad = make_float2(av[i], av[i]);
                acc[i][0] = ffma2(ad, b20, acc[i][0]);
                acc[i][1] = ffma2(ad, b21, acc[i][1]);
            }
        }
        __syncthreads();
    }
#pragma unroll
    for (int i = 0; i < 4; i++) {
        int m = m0 + ty * 4 + i;
        float* orow = g_wzh + (size_t)m * HH_ + n0 + tx * 4;
        int n = n0 + tx * 4;
        orow[0] = acc[i][0].x * g_scale[n + 0] + g_bias[n + 0];
        orow[1] = acc[i][0].y * g_scale[n + 1] + g_bias[n + 1];
        orow[2] = acc[i][1].x * g_scale[n + 2] + g_bias[n + 2];
        orow[3] = acc[i][1].y * g_scale[n + 3] + g_bias[n + 3];
    }
}

// ---------------- common matvec body (h via float4 LDS) ----------------
#define MATVEC_BODY()                                                                  \
    float2 a0 = make_float2(0.f, 0.f), a1 = make_float2(0.f, 0.f);                     \
    {                                                                                  \
        const float4* h0 = (const float4*)&h_sm[0][c * 64];                            \
        const float4* h1 = (const float4*)&h_sm[1][c * 64];                            \
        _Pragma("unroll")                                                              \
        for (int q = 0; q < 16; q++) {                                                 \
            float4 v0 = h0[q];                                                         \
            float4 v1 = h1[q];                                                         \
            a0 = ffma2(Ureg[2 * q],     make_float2(v0.x, v0.y), a0);                  \
            a0 = ffma2(Ureg[2 * q + 1], make_float2(v0.z, v0.w), a0);                  \
            a1 = ffma2(Ureg[2 * q],     make_float2(v1.x, v1.y), a1);                  \
            a1 = ffma2(Ureg[2 * q + 1], make_float2(v1.z, v1.w), a1);                  \
        }                                                                              \
    }

// ---------------- phase 2a: cluster scan with DSMEM h-exchange ----------------
// 8 clusters x 16 CTAs. Cluster g owns batches {2g, 2g+1}. CTA ci holds U rows
// [32ci,+32) (z) and [512+32ci,+32) (h) in registers. Gate threads push their h
// value into every CTA's h_sm via st.shared::cluster; barrier.cluster orders it.
__global__ __launch_bounds__(512, 1) void scan_cluster(const float* __restrict__ U) {
    __shared__ __align__(16) float h_sm[2][512];
    __shared__ float red[2][8][64];

    int t   = threadIdx.x;
    int grp = blockIdx.x >> 4;
    int ci  = blockIdx.x & 15;
    int b0  = grp * 2;

    int r = t & 63;
    int c = t >> 6;
    int urow = (r < 32) ? (ci * 32 + r) : (512 + ci * 32 + (r - 32));

    const float2* Up = (const float2*)(U + (size_t)urow * 512 + c * 64);
    float2 Ureg[32];
#pragma unroll
    for (int q = 0; q < 32; q++) Ureg[q] = __ldg(&Up[q]);

    for (int idx = t; idx < 1024; idx += 512) ((float*)h_sm)[idx] = 0.f;

    int bb = t >> 5, j = t & 31;           // gate threads: t < 64
    int bcur = b0 + bb;
    int cz = ci * 32 + j, ch = 512 + ci * 32 + j;
    float nz = 0.f, nh = 0.f;
    uint32_t my_h_addr = 0;
    if (t < 64) {
        nz = __ldg(&g_wzh[(size_t)bcur * TT_ * HH_ + cz]);
        nh = __ldg(&g_wzh[(size_t)bcur * TT_ * HH_ + ch]);
        my_h_addr = smem_u32(&h_sm[bb][ci * 32 + j]);
    }
    __syncthreads();

    for (int s = 0; s < TT_; s++) {
        MATVEC_BODY();
        red[0][c][r] = a0.x + a0.y;
        red[1][c][r] = a1.x + a1.y;
        __syncthreads();

        if (t < 64) {
            float uz = 0.f, uh = 0.f;
#pragma unroll
            for (int cc = 0; cc < 8; cc++) { uz += red[bb][cc][j]; uh += red[bb][cc][32 + j]; }
            float zt = __fdividef(1.f, 1.f + __expf(-(nz + uz)));
            float hc = fmaxf(nh + uh, 0.f);
            float hp = h_sm[bb][ci * 32 + j];
            float hn = zt * hp + (1.f - zt) * hc;
            __stcg(&g_hseq[((size_t)bcur * TT_ + s) * H_ + ci * 32 + j], hn);
            // broadcast hn into every cluster CTA's h_sm (incl. own)
#pragma unroll
            for (int rk = 0; rk < 16; rk++) {
                uint32_t rem;
                asm volatile("mapa.shared::cluster.u32 %0, %1, %2;"
                             : "=r"(rem) : "r"(my_h_addr), "r"(rk));
                asm volatile("st.shared::cluster.f32 [%0], %1;" :: "r"(rem), "f"(hn) : "memory");
            }
            if (s + 1 < TT_) {
                nz = __ldg(&g_wzh[((size_t)bcur * TT_ + s + 1) * HH_ + cz]);
                nh = __ldg(&g_wzh[((size_t)bcur * TT_ + s + 1) * HH_ + ch]);
            }
        }
        // release peers' view of our stores / acquire theirs; also a full CTA barrier
        asm volatile("barrier.cluster.arrive.aligned;" ::: "memory");
        asm volatile("barrier.cluster.wait.aligned;"   ::: "memory");
    }
}

// ---------------- phase 2b: fallback scan (distributed epoch flags) ----------------
__global__ __launch_bounds__(512, 1) void scan_kernel(const float* __restrict__ U) {
    __shared__ __align__(16) float h_sm[2][512];
    __shared__ float red[2][8][64];

    int t   = threadIdx.x;
    int grp = blockIdx.x >> 4;
    int ci  = blockIdx.x & 15;
    int b0  = grp * 2;

    int r = t & 63;
    int c = t >> 6;
    int urow = (r < 32) ? (ci * 32 + r) : (512 + ci * 32 + (r - 32));

    const float2* Up = (const float2*)(U + (size_t)urow * 512 + c * 64);
    float2 Ureg[32];
#pragma unroll
    for (int q = 0; q < 32; q++) Ureg[q] = __ldg(&Up[q]);

    for (int idx = t; idx < 1024; idx += 512) ((float*)h_sm)[idx] = 0.f;

    int bb = t >> 5, j = t & 31;
    int bcur = b0 + bb;
    int cz = ci * 32 + j, ch = 512 + ci * 32 + j;
    float nz = 0.f, nh = 0.f;
    if (t < 64) {
        nz = __ldg(&g_wzh[(size_t)bcur * TT_ * HH_ + cz]);
        nh = __ldg(&g_wzh[(size_t)bcur * TT_ * HH_ + ch]);
    }
    __syncthreads();

    for (int s = 0; s < TT_; s++) {
        MATVEC_BODY();
        red[0][c][r] = a0.x + a0.y;
        red[1][c][r] = a1.x + a1.y;
        __syncthreads();

        if (t < 64) {
            float uz = 0.f, uh = 0.f;
#pragma unroll
            for (int cc = 0; cc < 8; cc++) { uz += red[bb][cc][j]; uh += red[bb][cc][32 + j]; }
            float zt = __fdividef(1.f, 1.f + __expf(-(nz + uz)));
            float hc = fmaxf(nh + uh, 0.f);
            float hp = h_sm[bb][ci * 32 + j];
            float hn = zt * hp + (1.f - zt) * hc;
            __stcg(&g_hseq[((size_t)bcur * TT_ + s) * H_ + ci * 32 + j], hn);
            if (s + 1 < TT_) {
                nz = __ldg(&g_wzh[((size_t)bcur * TT_ + s + 1) * HH_ + cz]);
                nh = __ldg(&g_wzh[((size_t)bcur * TT_ + s + 1) * HH_ + ch]);
            }
        }
        __syncthreads();
        // release: fence + epoch flag in own 128B line
        if (t == 0) {
            __threadfence();
            asm volatile("st.relaxed.gpu.u32 [%0], %1;"
                         :: "l"(&g_flag[(grp * 16 + ci) * 32]), "r"((unsigned)(s + 1)) : "memory");
        }
        // acquire: 16 threads poll 16 distinct lines in parallel
        if (t < 16) {
            unsigned v;
            const unsigned int* f = &g_flag[(grp * 16 + t) * 32];
            do {
                asm volatile("ld.acquire.gpu.u32 %0, [%1];" : "=r"(v) : "l"(f) : "memory");
            } while (v < (unsigned)(s + 1));
        }
        __syncthreads();
        // reload h (both batches) from L2, float4
        if (t < 256) {
            int b2 = t >> 7;            // 0..1
            int hh = (t & 127) << 2;    // 0..508 step 4
            const float4* src = (const float4*)&g_hseq[((size_t)(b0 + b2) * TT_ + s) * H_ + hh];
            float4 v = __ldcg(src);
            *(float4*)&h_sm[b2][hh] = v;
        }
        __syncthreads();
    }
}

// ---------------- phase 3: LayerNorm ----------------
__global__ __launch_bounds__(256) void ln_kernel(const float* __restrict__ lng,
                                                 const float* __restrict__ lnb) {
    __shared__ float s_sum[8], s_sq[8];
    int row = blockIdx.x;
    int b = row / T_, tt = row - b * T_;
    int tid = threadIdx.x;
    int d = tid * 4;
    const float* base = (d < 512)
        ? (g_hseq + ((size_t)b * TT_ + tt) * H_ + d)
        : (g_hseq + ((size_t)(15 - b) * TT_ + T_ + tt) * H_ + (d - 512));
    float4 v = *(const float4*)base;
    float s = v.x + v.y + v.z + v.w;
    float q = v.x * v.x + v.y * v.y + v.z * v.z + v.w * v.w;
#pragma unroll
    for (int o = 16; o > 0; o >>= 1) {
        s += __shfl_down_sync(0xffffffffu, s, o);
        q += __shfl_down_sync(0xffffffffu, q, o);
    }
    int wid = tid >> 5, lid = tid & 31;
    if (lid == 0) { s_sum[wid] = s; s_sq[wid] = q; }
    __syncthreads();
    if (tid == 0) {
        float S = 0.f, Q = 0.f;
#pragma unroll
        for (int w = 0; w < 8; w++) { S += s_sum[w]; Q += s_sq[w]; }
        s_sum[0] = S; s_sq[0] = Q;
    }
    __syncthreads();
    float mu  = s_sum[0] * (1.f / 1024.f);
    float var = s_sq[0] * (1.f / 1024.f) - mu * mu;
    float inv = rsqrtf(var + 1e-5f);
    float4 g4 = *(const float4*)(lng + d);
    float4 b4 = *(const float4*)(lnb + d);
    float4 o;
    o.x = (v.x - mu) * inv * g4.x + b4.x;
    o.y = (v.y - mu) * inv * g4.y + b4.y;
    o.z = (v.z - mu) * inv * g4.z + b4.z;
    o.w = (v.w - mu) * inv * g4.w + b4.w;
    *(float4*)(g_ln + (size_t)row * HH_ + d) = o;
}

// ---------------- phase 4: out = tanh(ln @ pj_W^T + pj_b) ----------------
__global__ __launch_bounds__(256) void gemm_proj(const float* __restrict__ pjW,
                                                 const float* __restrict__ pjb,
                                                 float* __restrict__ out) {
    __shared__ __align__(16) float As[32][68];
    __shared__ __align__(16) float Bs[32][68];
    int tid = threadIdx.x;
    int tx = tid & 15, ty = tid >> 4;
    int m0 = blockIdx.y * 64, n0 = blockIdx.x * 64;

    float2 acc[4][2];
#pragma unroll
    for (int i = 0; i < 4; i++) { acc[i][0] = make_float2(0.f, 0.f); acc[i][1] = make_float2(0.f, 0.f); }

    for (int k0 = 0; k0 < 1024; k0 += 32) {
#pragma unroll
        for (int u = 0; u < 2; u++) {
            int v  = tid * 2 + u;
            int mm = v >> 3;
            int k4 = (v & 7) * 4;
            float4 av = *(const float4*)(g_ln + (size_t)(m0 + mm) * HH_ + k0 + k4);
            As[k4 + 0][mm] = av.x; As[k4 + 1][mm] = av.y; As[k4 + 2][mm] = av.z; As[k4 + 3][mm] = av.w;
            float4 bv = *(const float4*)(pjW + (size_t)(n0 + mm) * HH_ + k0 + k4);
            Bs[k4 + 0][mm] = bv.x; Bs[k4 + 1][mm] = bv.y; Bs[k4 + 2][mm] = bv.z; Bs[k4 + 3][mm] = bv.w;
        }
        __syncthreads();
#pragma unroll
        for (int k = 0; k < 32; k++) {
            float4 a4 = *(const float4*)&As[k][ty * 4];
            float4 b4 = *(const float4*)&Bs[k][tx * 4];
            float2 b20 = make_float2(b4.x, b4.y), b21 = make_float2(b4.z, b4.w);
            float av[4] = {a4.x, a4.y, a4.z, a4.w};
#pragma unroll
            for (int i = 0; i < 4; i++) {
                float2 ad = make_float2(av[i], av[i]);
                acc[i][0] = ffma2(ad, b20, acc[i][0]);
                acc[i][1] = ffma2(ad, b21, acc[i][1]);
            }
        }
        __syncthreads();
    }
#pragma unroll
    for (int i = 0; i < 4; i++) {
        int m = m0 + ty * 4 + i;
        int n = n0 + tx * 4;
        float* orow = out + (size_t)m * HH_ + n;
        orow[0] = tanhf(acc[i][0].x + pjb[n + 0]);
        orow[1] = tanhf(acc[i][0].y + pjb[n + 1]);
        orow[2] = tanhf(acc[i][1].x + pjb[n + 2]);
        orow[3] = tanhf(acc[i][1].y + pjb[n + 3]);
    }
}

// ---------------- tail: x_len pass-through ----------------
__global__ void tail_kernel(const int* __restrict__ xlen, float* __restrict__ out) {
    int t = threadIdx.x;
    if (t < B_) out[(size_t)B_ * T_ * HH_ + t] = (float)xlen[t];
}

extern "C" void kernel_launch(void* const* d_in, const int* in_sizes, int n_in,
                              void* d_out, int out_size) {
    const float* x   = (const float*)d_in[0];
    const int*   xl  = (const int*)  d_in[1];
    const float* Wz  = (const float*)d_in[2];
    const float* bz  = (const float*)d_in[3];
    const float* Wh  = (const float*)d_in[4];
    const float* bh  = (const float*)d_in[5];
    const float* U   = (const float*)d_in[6];
    const float* zg  = (const float*)d_in[7];
    const float* zb  = (const float*)d_in[8];
    const float* zm  = (const float*)d_in[9];
    const float* zv  = (const float*)d_in[10];
    const float* hg  = (const float*)d_in[11];
    const float* hb  = (const float*)d_in[12];
    const float* hm  = (const float*)d_in[13];
    const float* hv  = (const float*)d_in[14];
    const float* lng = (const float*)d_in[15];
    const float* lnb = (const float*)d_in[16];
    const float* pjW = (const float*)d_in[17];
    const float* pjb = (const float*)d_in[18];
    float* out = (float*)d_out;

    prep_kernel<<<1, 1024>>>(bz, bh, zg, zb, zm, zv, hg, hb, hm, hv);
    gemm_wzh<<<dim3(16, 500), 256>>>(x, Wz, Wh);

    // Cluster scan (8 independent 16-CTA clusters); fall back if unsupported.
    bool launched_cluster = false;
    {
        cudaError_t ea = cudaFuncSetAttribute(
            scan_cluster, cudaFuncAttributeNonPortableClusterSizeAllowed, 1);

        cudaLaunchConfig_t cfg = {};
        cfg.gridDim  = dim3(128, 1, 1);
        cfg.blockDim = dim3(512, 1, 1);
        cfg.dynamicSmemBytes = 0;
        cfg.stream = 0;
        cudaLaunchAttribute attrs[1];
        attrs[0].id = cudaLaunchAttributeClusterDimension;
        attrs[0].val.clusterDim.x = 16;
        attrs[0].val.clusterDim.y = 1;
        attrs[0].val.clusterDim.z = 1;
        cfg.attrs = attrs;
        cfg.numAttrs = 1;

        int maxClusters = 0;
        cudaError_t qe = cudaOccupancyMaxActiveClusters(&maxClusters, scan_cluster, &cfg);
        // Clusters are mutually independent -> any residency >=1 is deadlock-free.
        if (ea == cudaSuccess && qe == cudaSuccess && maxClusters >= 1) {
            cudaError_t le = cudaLaunchKernelEx(&cfg, scan_cluster, U);
            if (le == cudaSuccess) launched_cluster = true;
            else (void)cudaGetLastError();
        } else {
            (void)cudaGetLastError();
        }
    }
    if (!launched_cluster) {
        scan_kernel<<<128, 512>>>(U);
    }

    ln_kernel<<<16000, 256>>>(lng, lnb);
    gemm_proj<<<dim3(16, 250), 256>>>(pjW, pjb, out);
    if (out_size >= B_ * T_ * HH_ + B_) {
        tail_kernel<<<1, 32>>>(xl, out);
    }
    (void)in_sizes; (void)n_in;
}

// round 4
// speedup vs baseline: 1.1851x; 1.1851x over previous
#include <cuda_runtime.h>
#include <math.h>
#include <stdint.h>

// Problem constants (fixed shapes)
#define B_  16
#define T_  1000
#define TT_ 2000
#define F_  512
#define H_  512
#define HH_ 1024

// ---------------- device scratch ----------------
__device__ float g_wzh [B_ * TT_ * HH_];   // BN'd pre-activations
__device__ float g_hseq[B_ * TT_ * H_ ];   // hidden states over the 2000-step scan
__device__ float g_ln  [B_ * T_  * HH_];   // layernorm output
__device__ float g_scale[HH_];
__device__ float g_bias [HH_];
__device__ unsigned int g_flag[8 * 16 * 32];  // per-(group,CTA) epoch flags, 128B apart

// ---------------- packed fp32x2 FMA ----------------
__device__ __forceinline__ float2 ffma2(float2 a, float2 b, float2 c) {
    float2 d;
    asm("fma.rn.f32x2 %0, %1, %2, %3;"
        : "=l"(reinterpret_cast<unsigned long long &>(d))
        : "l"(reinterpret_cast<unsigned long long &>(a)),
          "l"(reinterpret_cast<unsigned long long &>(b)),
          "l"(reinterpret_cast<unsigned long long &>(c)));
    return d;
}

// ---------------- prep ----------------
__global__ void prep_kernel(const float* __restrict__ bz, const float* __restrict__ bh,
                            const float* __restrict__ zg, const float* __restrict__ zb,
                            const float* __restrict__ zm, const float* __restrict__ zv,
                            const float* __restrict__ hg, const float* __restrict__ hb,
                            const float* __restrict__ hm, const float* __restrict__ hv) {
    int n = threadIdx.x;  // 1024 threads
    float sc, bi;
    if (n < 512) {
        sc = zg[n] * rsqrtf(zv[n] + 1e-5f);
        bi = (bz[n] - zm[n]) * sc + zb[n];
    } else {
        int j = n - 512;
        sc = hg[j] * rsqrtf(hv[j] + 1e-5f);
        bi = (bh[j] - hm[j]) * sc + hb[j];
    }
    g_scale[n] = sc;
    g_bias[n]  = bi;
    for (int i = n; i < 8 * 16 * 32; i += 1024) g_flag[i] = 0u;
}

// ---------------- phase 1: wzh = BN(x_cat @ [Wz;Wh]^T + b) ----------------
__global__ __launch_bounds__(256) void gemm_wzh(const float* __restrict__ x,
                                                const float* __restrict__ Wz,
                                                const float* __restrict__ Wh) {
    __shared__ __align__(16) float As[32][68];
    __shared__ __align__(16) float Bs[32][68];
    int tid = threadIdx.x;
    int tx = tid & 15, ty = tid >> 4;
    int m0 = blockIdx.y * 64, n0 = blockIdx.x * 64;

    float2 acc[4][2];
#pragma unroll
    for (int i = 0; i < 4; i++) { acc[i][0] = make_float2(0.f, 0.f); acc[i][1] = make_float2(0.f, 0.f); }

    for (int k0 = 0; k0 < 512; k0 += 32) {
#pragma unroll
        for (int u = 0; u < 2; u++) {
            int v  = tid * 2 + u;
            int mm = v >> 3;
            int k4 = (v & 7) * 4;

            int m = m0 + mm;
            int b = m / TT_;
            int tp = m - b * TT_;
            const float* arow = (tp < T_) ? (x + ((size_t)(b * T_ + tp) << 9))
                                          : (x + ((size_t)((15 - b) * T_ + (tp - T_)) << 9));
            float4 av = *(const float4*)(arow + k0 + k4);
            As[k4 + 0][mm] = av.x; As[k4 + 1][mm] = av.y; As[k4 + 2][mm] = av.z; As[k4 + 3][mm] = av.w;

            int n = n0 + mm;
            const float* brow = (n < 512) ? (Wz + ((size_t)n << 9))
                                          : (Wh + ((size_t)(n - 512) << 9));
            float4 bv = *(const float4*)(brow + k0 + k4);
            Bs[k4 + 0][mm] = bv.x; Bs[k4 + 1][mm] = bv.y; Bs[k4 + 2][mm] = bv.z; Bs[k4 + 3][mm] = bv.w;
        }
        __syncthreads();
#pragma unroll
        for (int k = 0; k < 32; k++) {
            float4 a4 = *(const float4*)&As[k][ty * 4];
            float4 b4 = *(const float4*)&Bs[k][tx * 4];
            float2 b20 = make_float2(b4.x, b4.y), b21 = make_float2(b4.z, b4.w);
            float av[4] = {a4.x, a4.y, a4.z, a4.w};
#pragma unroll
            for (int i = 0; i < 4; i++) {
                float2 ad = make_float2(av[i], av[i]);
                acc[i][0] = ffma2(ad, b20, acc[i][0]);
                acc[i][1] = ffma2(ad, b21, acc[i][1]);
            }
        }
        __syncthreads();
    }
#pragma unroll
    for (int i = 0; i < 4; i++) {
        int m = m0 + ty * 4 + i;
        float* orow = g_wzh + (size_t)m * HH_ + n0 + tx * 4;
        int n = n0 + tx * 4;
        orow[0] = acc[i][0].x * g_scale[n + 0] + g_bias[n + 0];
        orow[1] = acc[i][0].y * g_scale[n + 1] + g_bias[n + 1];
        orow[2] = acc[i][1].x * g_scale[n + 2] + g_bias[n + 2];
        orow[3] = acc[i][1].y * g_scale[n + 3] + g_bias[n + 3];
    }
}

// ---------------- phase 2: persistent scan (distributed epoch-flag sync) ----------------
// 128 CTAs = 8 groups x 16 CTAs. Group g owns batches {2g, 2g+1}.
// CTA ci holds U rows [32ci,+32) (z) and [512+32ci,+32) (h) in registers.
// Per-step handoff: stcg h slice -> L2; st.release per-CTA epoch flag (own 128B
// line); 16 threads acquire-poll the 16 flags in parallel; ldcg h reload.
__global__ __launch_bounds__(512, 1) void scan_kernel(const float* __restrict__ U) {
    __shared__ __align__(16) float h_sm[2][512];
    __shared__ float red[2][8][64];

    int t   = threadIdx.x;
    int grp = blockIdx.x >> 4;
    int ci  = blockIdx.x & 15;
    int b0  = grp * 2;

    int r = t & 63;              // local row 0..63 (0..31 z, 32..63 h)
    int c = t >> 6;              // k-chunk 0..7 (64 k each)
    int urow = (r < 32) ? (ci * 32 + r) : (512 + ci * 32 + (r - 32));

    const float2* Up = (const float2*)(U + (size_t)urow * 512 + c * 64);
    float2 Ureg[32];
#pragma unroll
    for (int q = 0; q < 32; q++) Ureg[q] = __ldg(&Up[q]);

    for (int idx = t; idx < 1024; idx += 512) ((float*)h_sm)[idx] = 0.f;

    int bb = t >> 5, j = t & 31;           // gate threads: t < 64
    int bcur = b0 + bb;
    int cz = ci * 32 + j, ch = 512 + ci * 32 + j;
    float nz = 0.f, nh = 0.f;
    if (t < 64) {
        nz = __ldg(&g_wzh[(size_t)bcur * TT_ * HH_ + cz]);
        nh = __ldg(&g_wzh[(size_t)bcur * TT_ * HH_ + ch]);
    }
    __syncthreads();

    for (int s = 0; s < TT_; s++) {
        // matvec over this thread's 64-k chunk, both batches (float4 LDS broadcasts)
        float2 a0 = make_float2(0.f, 0.f), a1 = make_float2(0.f, 0.f);
        {
            const float4* h0 = (const float4*)&h_sm[0][c * 64];
            const float4* h1 = (const float4*)&h_sm[1][c * 64];
#pragma unroll
            for (int q = 0; q < 16; q++) {
                float4 v0 = h0[q];
                float4 v1 = h1[q];
                a0 = ffma2(Ureg[2 * q],     make_float2(v0.x, v0.y), a0);
                a0 = ffma2(Ureg[2 * q + 1], make_float2(v0.z, v0.w), a0);
                a1 = ffma2(Ureg[2 * q],     make_float2(v1.x, v1.y), a1);
                a1 = ffma2(Ureg[2 * q + 1], make_float2(v1.z, v1.w), a1);
            }
        }
        red[0][c][r] = a0.x + a0.y;
        red[1][c][r] = a1.x + a1.y;
        __syncthreads();

        if (t < 64) {
            float uz = 0.f, uh = 0.f;
#pragma unroll
            for (int cc = 0; cc < 8; cc++) { uz += red[bb][cc][j]; uh += red[bb][cc][32 + j]; }
            float zt = __fdividef(1.f, 1.f + __expf(-(nz + uz)));
            float hc = fmaxf(nh + uh, 0.f);
            float hp = h_sm[bb][ci * 32 + j];
            float hn = zt * hp + (1.f - zt) * hc;
            __stcg(&g_hseq[((size_t)bcur * TT_ + s) * H_ + ci * 32 + j], hn);
            if (s + 1 < TT_) {
                nz = __ldg(&g_wzh[((size_t)bcur * TT_ + s + 1) * HH_ + cz]);
                nh = __ldg(&g_wzh[((size_t)bcur * TT_ + s + 1) * HH_ + ch]);
            }
        }
        __syncthreads();   // all 64 gate stores issued before the release below
        // release: one per-CTA epoch flag in its own 128B line (orders prior stores)
        if (t == 0) {
            asm volatile("st.release.gpu.u32 [%0], %1;"
                         :: "l"(&g_flag[(grp * 16 + ci) * 32]), "r"((unsigned)(s + 1)) : "memory");
        }
        // acquire: 16 threads poll the 16 group flags concurrently (distinct lines)
        if (t < 16) {
            unsigned v;
            const unsigned int* f = &g_flag[(grp * 16 + t) * 32];
            do {
                asm volatile("ld.acquire.gpu.u32 %0, [%1];" : "=r"(v) : "l"(f) : "memory");
            } while (v < (unsigned)(s + 1));
        }
        __syncthreads();
        // reload h (both batches) from L2, float4
        if (t < 256) {
            int b2 = t >> 7;            // 0..1
            int hh = (t & 127) << 2;    // 0..508 step 4
            const float4* src = (const float4*)&g_hseq[((size_t)(b0 + b2) * TT_ + s) * H_ + hh];
            float4 v = __ldcg(src);
            *(float4*)&h_sm[b2][hh] = v;
        }
        __syncthreads();
    }
}

// ---------------- phase 3: LayerNorm ----------------
__global__ __launch_bounds__(256) void ln_kernel(const float* __restrict__ lng,
                                                 const float* __restrict__ lnb) {
    __shared__ float s_sum[8], s_sq[8];
    int row = blockIdx.x;
    int b = row / T_, tt = row - b * T_;
    int tid = threadIdx.x;
    int d = tid * 4;
    const float* base = (d < 512)
        ? (g_hseq + ((size_t)b * TT_ + tt) * H_ + d)
        : (g_hseq + ((size_t)(15 - b) * TT_ + T_ + tt) * H_ + (d - 512));
    float4 v = *(const float4*)base;
    float s = v.x + v.y + v.z + v.w;
    float q = v.x * v.x + v.y * v.y + v.z * v.z + v.w * v.w;
#pragma unroll
    for (int o = 16; o > 0; o >>= 1) {
        s += __shfl_down_sync(0xffffffffu, s, o);
        q += __shfl_down_sync(0xffffffffu, q, o);
    }
    int wid = tid >> 5, lid = tid & 31;
    if (lid == 0) { s_sum[wid] = s; s_sq[wid] = q; }
    __syncthreads();
    if (tid == 0) {
        float S = 0.f, Q = 0.f;
#pragma unroll
        for (int w = 0; w < 8; w++) { S += s_sum[w]; Q += s_sq[w]; }
        s_sum[0] = S; s_sq[0] = Q;
    }
    __syncthreads();
    float mu  = s_sum[0] * (1.f / 1024.f);
    float var = s_sq[0] * (1.f / 1024.f) - mu * mu;
    float inv = rsqrtf(var + 1e-5f);
    float4 g4 = *(const float4*)(lng + d);
    float4 b4 = *(const float4*)(lnb + d);
    float4 o;
    o.x = (v.x - mu) * inv * g4.x + b4.x;
    o.y = (v.y - mu) * inv * g4.y + b4.y;
    o.z = (v.z - mu) * inv * g4.z + b4.z;
    o.w = (v.w - mu) * inv * g4.w + b4.w;
    *(float4*)(g_ln + (size_t)row * HH_ + d) = o;
}

// ---------------- phase 4: out = tanh(ln @ pj_W^T + pj_b) ----------------
__global__ __launch_bounds__(256) void gemm_proj(const float* __restrict__ pjW,
                                                 const float* __restrict__ pjb,
                                                 float* __restrict__ out) {
    __shared__ __align__(16) float As[32][68];
    __shared__ __align__(16) float Bs[32][68];
    int tid = threadIdx.x;
    int tx = tid & 15, ty = tid >> 4;
    int m0 = blockIdx.y * 64, n0 = blockIdx.x * 64;

    float2 acc[4][2];
#pragma unroll
    for (int i = 0; i < 4; i++) { acc[i][0] = make_float2(0.f, 0.f); acc[i][1] = make_float2(0.f, 0.f); }

    for (int k0 = 0; k0 < 1024; k0 += 32) {
#pragma unroll
        for (int u = 0; u < 2; u++) {
            int v  = tid * 2 + u;
            int mm = v >> 3;
            int k4 = (v & 7) * 4;
            float4 av = *(const float4*)(g_ln + (size_t)(m0 + mm) * HH_ + k0 + k4);
            As[k4 + 0][mm] = av.x; As[k4 + 1][mm] = av.y; As[k4 + 2][mm] = av.z; As[k4 + 3][mm] = av.w;
            float4 bv = *(const float4*)(pjW + (size_t)(n0 + mm) * HH_ + k0 + k4);
            Bs[k4 + 0][mm] = bv.x; Bs[k4 + 1][mm] = bv.y; Bs[k4 + 2][mm] = bv.z; Bs[k4 + 3][mm] = bv.w;
        }
        __syncthreads();
#pragma unroll
        for (int k = 0; k < 32; k++) {
            float4 a4 = *(const float4*)&As[k][ty * 4];
            float4 b4 = *(const float4*)&Bs[k][tx * 4];
            float2 b20 = make_float2(b4.x, b4.y), b21 = make_float2(b4.z, b4.w);
            float av[4] = {a4.x, a4.y, a4.z, a4.w};
#pragma unroll
            for (int i = 0; i < 4; i++) {
                float2 ad = make_float2(av[i], av[i]);
                acc[i][0] = ffma2(ad, b20, acc[i][0]);
                acc[i][1] = ffma2(ad, b21, acc[i][1]);
            }
        }
        __syncthreads();
    }
#pragma unroll
    for (int i = 0; i < 4; i++) {
        int m = m0 + ty * 4 + i;
        int n = n0 + tx * 4;
        float* orow = out + (size_t)m * HH_ + n;
        orow[0] = tanhf(acc[i][0].x + pjb[n + 0]);
        orow[1] = tanhf(acc[i][0].y + pjb[n + 1]);
        orow[2] = tanhf(acc[i][1].x + pjb[n + 2]);
        orow[3] = tanhf(acc[i][1].y + pjb[n + 3]);
    }
}

// ---------------- tail: x_len pass-through ----------------
__global__ void tail_kernel(const int* __restrict__ xlen, float* __restrict__ out) {
    int t = threadIdx.x;
    if (t < B_) out[(size_t)B_ * T_ * HH_ + t] = (float)xlen[t];
}

extern "C" void kernel_launch(void* const* d_in, const int* in_sizes, int n_in,
                              void* d_out, int out_size) {
    const float* x   = (const float*)d_in[0];
    const int*   xl  = (const int*)  d_in[1];
    const float* Wz  = (const float*)d_in[2];
    const float* bz  = (const float*)d_in[3];
    const float* Wh  = (const float*)d_in[4];
    const float* bh  = (const float*)d_in[5];
    const float* U   = (const float*)d_in[6];
    const float* zg  = (const float*)d_in[7];
    const float* zb  = (const float*)d_in[8];
    const float* zm  = (const float*)d_in[9];
    const float* zv  = (const float*)d_in[10];
    const float* hg  = (const float*)d_in[11];
    const float* hb  = (const float*)d_in[12];
    const float* hm  = (const float*)d_in[13];
    const float* hv  = (const float*)d_in[14];
    const float* lng = (const float*)d_in[15];
    const float* lnb = (const float*)d_in[16];
    const float* pjW = (const float*)d_in[17];
    const float* pjb = (const float*)d_in[18];
    float* out = (float*)d_out;

    prep_kernel<<<1, 1024>>>(bz, bh, zg, zb, zm, zv, hg, hb, hm, hv);
    gemm_wzh<<<dim3(16, 500), 256>>>(x, Wz, Wh);
    scan_kernel<<<128, 512>>>(U);
    ln_kernel<<<16000, 256>>>(lng, lnb);
    gemm_proj<<<dim3(16, 250), 256>>>(pjW, pjb, out);
    if (out_size >= B_ * T_ * HH_ + B_) {
        tail_kernel<<<1, 32>>>(xl, out);
    }
    (void)in_sizes; (void)n_in;
}

// round 5
// speedup vs baseline: 1.4079x; 1.1880x over previous
#include <cuda_runtime.h>
#include <math.h>
#include <stdint.h>

// Problem constants (fixed shapes)
#define B_  16
#define T_  1000
#define TT_ 2000
#define F_  512
#define H_  512
#define HH_ 1024

// ---------------- device scratch ----------------
__device__ float g_wzh [B_ * TT_ * HH_];   // BN'd pre-activations
__device__ float g_hseq[B_ * TT_ * H_ ];   // hidden states over the 2000-step scan
__device__ float g_ln  [B_ * T_  * HH_];   // layernorm output
__device__ float g_scale[HH_];
__device__ float g_bias [HH_];
// tagged-value mailbox: [parity][group][slot]; slot = ci*64 + bb*32 + j
// packet = (tag:u32 << 32) | f32 bits of h. Double-buffered by step parity.
__device__ unsigned long long g_mail[2][8][1024];

// ---------------- packed fp32x2 FMA ----------------
__device__ __forceinline__ float2 ffma2(float2 a, float2 b, float2 c) {
    float2 d;
    asm("fma.rn.f32x2 %0, %1, %2, %3;"
        : "=l"(reinterpret_cast<unsigned long long &>(d))
        : "l"(reinterpret_cast<unsigned long long &>(a)),
          "l"(reinterpret_cast<unsigned long long &>(b)),
          "l"(reinterpret_cast<unsigned long long &>(c)));
    return d;
}

// ---------------- prep: fold BN; zero mailbox ----------------
__global__ void prep_kernel(const float* __restrict__ bz, const float* __restrict__ bh,
                            const float* __restrict__ zg, const float* __restrict__ zb,
                            const float* __restrict__ zm, const float* __restrict__ zv,
                            const float* __restrict__ hg, const float* __restrict__ hb,
                            const float* __restrict__ hm, const float* __restrict__ hv) {
    int n = threadIdx.x;  // 1024 threads
    float sc, bi;
    if (n < 512) {
        sc = zg[n] * rsqrtf(zv[n] + 1e-5f);
        bi = (bz[n] - zm[n]) * sc + zb[n];
    } else {
        int j = n - 512;
        sc = hg[j] * rsqrtf(hv[j] + 1e-5f);
        bi = (bh[j] - hm[j]) * sc + hb[j];
    }
    g_scale[n] = sc;
    g_bias[n]  = bi;
    unsigned long long* mp = &g_mail[0][0][0];
    for (int i = n; i < 2 * 8 * 1024; i += 1024) mp[i] = 0ull;
}

// ---------------- dummy: shifts ncu capture index onto scan_kernel ----------------
__global__ void dummy_kernel() {}

// ---------------- phase 1: wzh = BN(x_cat @ [Wz;Wh]^T + b) ----------------
__global__ __launch_bounds__(256) void gemm_wzh(const float* __restrict__ x,
                                                const float* __restrict__ Wz,
                                                const float* __restrict__ Wh) {
    __shared__ __align__(16) float As[32][68];
    __shared__ __align__(16) float Bs[32][68];
    int tid = threadIdx.x;
    int tx = tid & 15, ty = tid >> 4;
    int m0 = blockIdx.y * 64, n0 = blockIdx.x * 64;

    float2 acc[4][2];
#pragma unroll
    for (int i = 0; i < 4; i++) { acc[i][0] = make_float2(0.f, 0.f); acc[i][1] = make_float2(0.f, 0.f); }

    for (int k0 = 0; k0 < 512; k0 += 32) {
#pragma unroll
        for (int u = 0; u < 2; u++) {
            int v  = tid * 2 + u;
            int mm = v >> 3;
            int k4 = (v & 7) * 4;

            int m = m0 + mm;
            int b = m / TT_;
            int tp = m - b * TT_;
            const float* arow = (tp < T_) ? (x + ((size_t)(b * T_ + tp) << 9))
                                          : (x + ((size_t)((15 - b) * T_ + (tp - T_)) << 9));
            float4 av = *(const float4*)(arow + k0 + k4);
            As[k4 + 0][mm] = av.x; As[k4 + 1][mm] = av.y; As[k4 + 2][mm] = av.z; As[k4 + 3][mm] = av.w;

            int n = n0 + mm;
            const float* brow = (n < 512) ? (Wz + ((size_t)n << 9))
                                          : (Wh + ((size_t)(n - 512) << 9));
            float4 bv = *(const float4*)(brow + k0 + k4);
            Bs[k4 + 0][mm] = bv.x; Bs[k4 + 1][mm] = bv.y; Bs[k4 + 2][mm] = bv.z; Bs[k4 + 3][mm] = bv.w;
        }
        __syncthreads();
#pragma unroll
        for (int k = 0; k < 32; k++) {
            float4 a4 = *(const float4*)&As[k][ty * 4];
            float4 b4 = *(const float4*)&Bs[k][tx * 4];
            float2 b20 = make_float2(b4.x, b4.y), b21 = make_float2(b4.z, b4.w);
            float av[4] = {a4.x, a4.y, a4.z, a4.w};
#pragma unroll
            for (int i = 0; i < 4; i++) {
                float2 ad = make_float2(av[i], av[i]);
                acc[i][0] = ffma2(ad, b20, acc[i][0]);
                acc[i][1] = ffma2(ad, b21, acc[i][1]);
            }
        }
        __syncthreads();
    }
#pragma unroll
    for (int i = 0; i < 4; i++) {
        int m = m0 + ty * 4 + i;
        float* orow = g_wzh + (size_t)m * HH_ + n0 + tx * 4;
        int n = n0 + tx * 4;
        orow[0] = acc[i][0].x * g_scale[n + 0] + g_bias[n + 0];
        orow[1] = acc[i][0].y * g_scale[n + 1] + g_bias[n + 1];
        orow[2] = acc[i][1].x * g_scale[n + 2] + g_bias[n + 2];
        orow[3] = acc[i][1].y * g_scale[n + 3] + g_bias[n + 3];
    }
}

// ---------------- phase 2: persistent scan (single-hop tagged-mailbox sync) ----------------
// 128 CTAs = 8 groups x 16 CTAs. Group g owns batches {2g, 2g+1}.
// CTA ci holds U rows [32ci,+32) (z) and [512+32ci,+32) (h) in registers.
// Exchange: gate thread packs {tag=s+1, h} into one u64, st.release to mailbox;
// every thread acquire-polls 2 packets (tag>=s+1) and writes h into smem.
__global__ __launch_bounds__(512, 1) void scan_kernel(const float* __restrict__ U) {
    __shared__ __align__(16) float h_sm[2][512];
    __shared__ float red[2][8][64];

    int t   = threadIdx.x;
    int grp = blockIdx.x >> 4;
    int ci  = blockIdx.x & 15;
    int b0  = grp * 2;

    int r = t & 63;              // local row 0..63 (0..31 z, 32..63 h)
    int c = t >> 6;              // k-chunk 0..7 (64 k each)
    int urow = (r < 32) ? (ci * 32 + r) : (512 + ci * 32 + (r - 32));

    const float2* Up = (const float2*)(U + (size_t)urow * 512 + c * 64);
    float2 Ureg[32];
#pragma unroll
    for (int q = 0; q < 32; q++) Ureg[q] = __ldg(&Up[q]);

    for (int idx = t; idx < 1024; idx += 512) ((float*)h_sm)[idx] = 0.f;

    int bb = t >> 5, j = t & 31;           // gate threads: t < 64
    int bcur = b0 + bb;
    int cz = ci * 32 + j, ch = 512 + ci * 32 + j;
    float nz = 0.f, nh = 0.f;
    if (t < 64) {
        nz = __ldg(&g_wzh[(size_t)bcur * TT_ * HH_ + cz]);
        nh = __ldg(&g_wzh[(size_t)bcur * TT_ * HH_ + ch]);
    }
    // poll slots for this thread: m1 = t, m2 = t + 512
    int m1 = t, m2 = t + 512;
    int d1 = ((m1 >> 5) & 1), h1i = (((m1 >> 6) << 5) | (m1 & 31));
    int d2 = ((m2 >> 5) & 1), h2i = (((m2 >> 6) << 5) | (m2 & 31));
    __syncthreads();

    for (int s = 0; s < TT_; s++) {
        // matvec over this thread's 64-k chunk, both batches (float4 LDS broadcasts)
        float2 a0 = make_float2(0.f, 0.f), a1 = make_float2(0.f, 0.f);
        {
            const float4* h0 = (const float4*)&h_sm[0][c * 64];
            const float4* h1 = (const float4*)&h_sm[1][c * 64];
#pragma unroll
            for (int q = 0; q < 16; q++) {
                float4 v0 = h0[q];
                float4 v1 = h1[q];
                a0 = ffma2(Ureg[2 * q],     make_float2(v0.x, v0.y), a0);
                a0 = ffma2(Ureg[2 * q + 1], make_float2(v0.z, v0.w), a0);
                a1 = ffma2(Ureg[2 * q],     make_float2(v1.x, v1.y), a1);
                a1 = ffma2(Ureg[2 * q + 1], make_float2(v1.z, v1.w), a1);
            }
        }
        red[0][c][r] = a0.x + a0.y;
        red[1][c][r] = a1.x + a1.y;
        __syncthreads();   // matvec reads + red writes complete

        unsigned tag = (unsigned)(s + 1);
        int par = (s + 1) & 1;

        if (t < 64) {
            float uz = 0.f, uh = 0.f;
#pragma unroll
            for (int cc = 0; cc < 8; cc++) { uz += red[bb][cc][j]; uh += red[bb][cc][32 + j]; }
            float zt = __fdividef(1.f, 1.f + __expf(-(nz + uz)));
            float hc = fmaxf(nh + uh, 0.f);
            float hp = h_sm[bb][ci * 32 + j];
            float hn = zt * hp + (1.f - zt) * hc;
            __stcg(&g_hseq[((size_t)bcur * TT_ + s) * H_ + ci * 32 + j], hn);
            if (s + 1 < TT_) {
                // publish tagged packet: single-hop release (orders the hp read too)
                unsigned long long pkt =
                    ((unsigned long long)tag << 32) | (unsigned long long)__float_as_uint(hn);
                asm volatile("st.release.gpu.u64 [%0], %1;"
                             :: "l"(&g_mail[par][grp][ci * 64 + t]), "l"(pkt) : "memory");
                nz = __ldg(&g_wzh[((size_t)bcur * TT_ + s + 1) * HH_ + cz]);
                nh = __ldg(&g_wzh[((size_t)bcur * TT_ + s + 1) * HH_ + ch]);
            }
        }

        if (s + 1 < TT_) {
            // acquire-poll both packets concurrently; write h into smem for next step
            const unsigned long long* p1 = &g_mail[par][grp][m1];
            const unsigned long long* p2 = &g_mail[par][grp][m2];
            unsigned long long v1v = 0, v2v = 0;
            bool ok1 = false, ok2 = false;
            do {
                if (!ok1) {
                    asm volatile("ld.acquire.gpu.u64 %0, [%1];" : "=l"(v1v) : "l"(p1) : "memory");
                    ok1 = ((unsigned)(v1v >> 32)) >= tag;
                }
                if (!ok2) {
                    asm volatile("ld.acquire.gpu.u64 %0, [%1];" : "=l"(v2v) : "l"(p2) : "memory");
                    ok2 = ((unsigned)(v2v >> 32)) >= tag;
                }
            } while (!(ok1 && ok2));
            h_sm[d1][h1i] = __uint_as_float((unsigned)v1v);
            h_sm[d2][h2i] = __uint_as_float((unsigned)v2v);
            __syncthreads();   // all h_sm updates visible before next matvec
        }
    }
}

// ---------------- phase 3: LayerNorm ----------------
__global__ __launch_bounds__(256) void ln_kernel(const float* __restrict__ lng,
                                                 const float* __restrict__ lnb) {
    __shared__ float s_sum[8], s_sq[8];
    int row = blockIdx.x;
    int b = row / T_, tt = row - b * T_;
    int tid = threadIdx.x;
    int d = tid * 4;
    const float* base = (d < 512)
        ? (g_hseq + ((size_t)b * TT_ + tt) * H_ + d)
        : (g_hseq + ((size_t)(15 - b) * TT_ + T_ + tt) * H_ + (d - 512));
    float4 v = *(const float4*)base;
    float s = v.x + v.y + v.z + v.w;
    float q = v.x * v.x + v.y * v.y + v.z * v.z + v.w * v.w;
#pragma unroll
    for (int o = 16; o > 0; o >>= 1) {
        s += __shfl_down_sync(0xffffffffu, s, o);
        q += __shfl_down_sync(0xffffffffu, q, o);
    }
    int wid = tid >> 5, lid = tid & 31;
    if (lid == 0) { s_sum[wid] = s; s_sq[wid] = q; }
    __syncthreads();
    if (tid == 0) {
        float S = 0.f, Q = 0.f;
#pragma unroll
        for (int w = 0; w < 8; w++) { S += s_sum[w]; Q += s_sq[w]; }
        s_sum[0] = S; s_sq[0] = Q;
    }
    __syncthreads();
    float mu  = s_sum[0] * (1.f / 1024.f);
    float var = s_sq[0] * (1.f / 1024.f) - mu * mu;
    float inv = rsqrtf(var + 1e-5f);
    float4 g4 = *(const float4*)(lng + d);
    float4 b4 = *(const float4*)(lnb + d);
    float4 o;
    o.x = (v.x - mu) * inv * g4.x + b4.x;
    o.y = (v.y - mu) * inv * g4.y + b4.y;
    o.z = (v.z - mu) * inv * g4.z + b4.z;
    o.w = (v.w - mu) * inv * g4.w + b4.w;
    *(float4*)(g_ln + (size_t)row * HH_ + d) = o;
}

// ---------------- phase 4: out = tanh(ln @ pj_W^T + pj_b) ----------------
__global__ __launch_bounds__(256) void gemm_proj(const float* __restrict__ pjW,
                                                 const float* __restrict__ pjb,
                                                 float* __restrict__ out) {
    __shared__ __align__(16) float As[32][68];
    __shared__ __align__(16) float Bs[32][68];
    int tid = threadIdx.x;
    int tx = tid & 15, ty = tid >> 4;
    int m0 = blockIdx.y * 64, n0 = blockIdx.x * 64;

    float2 acc[4][2];
#pragma unroll
    for (int i = 0; i < 4; i++) { acc[i][0] = make_float2(0.f, 0.f); acc[i][1] = make_float2(0.f, 0.f); }

    for (int k0 = 0; k0 < 1024; k0 += 32) {
#pragma unroll
        for (int u = 0; u < 2; u++) {
            int v  = tid * 2 + u;
            int mm = v >> 3;
            int k4 = (v & 7) * 4;
            float4 av = *(const float4*)(g_ln + (size_t)(m0 + mm) * HH_ + k0 + k4);
            As[k4 + 0][mm] = av.x; As[k4 + 1][mm] = av.y; As[k4 + 2][mm] = av.z; As[k4 + 3][mm] = av.w;
            float4 bv = *(const float4*)(pjW + (size_t)(n0 + mm) * HH_ + k0 + k4);
            Bs[k4 + 0][mm] = bv.x; Bs[k4 + 1][mm] = bv.y; Bs[k4 + 2][mm] = bv.z; Bs[k4 + 3][mm] = bv.w;
        }
        __syncthreads();
#pragma unroll
        for (int k = 0; k < 32; k++) {
            float4 a4 = *(const float4*)&As[k][ty * 4];
            float4 b4 = *(const float4*)&Bs[k][tx * 4];
            float2 b20 = make_float2(b4.x, b4.y), b21 = make_float2(b4.z, b4.w);
            float av[4] = {a4.x, a4.y, a4.z, a4.w};
#pragma unroll
            for (int i = 0; i < 4; i++) {
                float2 ad = make_float2(av[i], av[i]);
                acc[i][0] = ffma2(ad, b20, acc[i][0]);
                acc[i][1] = ffma2(ad, b21, acc[i][1]);
            }
        }
        __syncthreads();
    }
#pragma unroll
    for (int i = 0; i < 4; i++) {
        int m = m0 + ty * 4 + i;
        int n = n0 + tx * 4;
        float* orow = out + (size_t)m * HH_ + n;
        orow[0] = tanhf(acc[i][0].x + pjb[n + 0]);
        orow[1] = tanhf(acc[i][0].y + pjb[n + 1]);
        orow[2] = tanhf(acc[i][1].x + pjb[n + 2]);
        orow[3] = tanhf(acc[i][1].y + pjb[n + 3]);
    }
}

// ---------------- tail: x_len pass-through ----------------
__global__ void tail_kernel(const int* __restrict__ xlen, float* __restrict__ out) {
    int t = threadIdx.x;
    if (t < B_) out[(size_t)B_ * T_ * HH_ + t] = (float)xlen[t];
}

extern "C" void kernel_launch(void* const* d_in, const int* in_sizes, int n_in,
                              void* d_out, int out_size) {
    const float* x   = (const float*)d_in[0];
    const int*   xl  = (const int*)  d_in[1];
    const float* Wz  = (const float*)d_in[2];
    const float* bz  = (const float*)d_in[3];
    const float* Wh  = (const float*)d_in[4];
    const float* bh  = (const float*)d_in[5];
    const float* U   = (const float*)d_in[6];
    const float* zg  = (const float*)d_in[7];
    const float* zb  = (const float*)d_in[8];
    const float* zm  = (const float*)d_in[9];
    const float* zv  = (const float*)d_in[10];
    const float* hg  = (const float*)d_in[11];
    const float* hb  = (const float*)d_in[12];
    const float* hm  = (const float*)d_in[13];
    const float* hv  = (const float*)d_in[14];
    const float* lng = (const float*)d_in[15];
    const float* lnb = (const float*)d_in[16];
    const float* pjW = (const float*)d_in[17];
    const float* pjb = (const float*)d_in[18];
    float* out = (float*)d_out;

    prep_kernel<<<1, 1024>>>(bz, bh, zg, zb, zm, zv, hg, hb, hm, hv);
    gemm_wzh<<<dim3(16, 500), 256>>>(x, Wz, Wh);
    dummy_kernel<<<1, 32>>>();            // shifts ncu capture onto scan_kernel
    scan_kernel<<<128, 512>>>(U);
    ln_kernel<<<16000, 256>>>(lng, lnb);
    gemm_proj<<<dim3(16, 250), 256>>>(pjW, pjb, out);
    if (out_size >= B_ * T_ * HH_ + B_) {
        tail_kernel<<<1, 32>>>(xl, out);
    }
    (void)in_sizes; (void)n_in;
}

// round 6
// speedup vs baseline: 1.7571x; 1.2480x over previous
#include <cuda_runtime.h>
#include <math.h>
#include <stdint.h>

// Problem constants (fixed shapes)
#define B_  16
#define T_  1000
#define TT_ 2000
#define F_  512
#define H_  512
#define HH_ 1024

// ---------------- device scratch ----------------
__device__ float g_wzh [B_ * TT_ * HH_];   // BN'd pre-activations
__device__ float g_hseq[B_ * TT_ * H_ ];   // hidden states over the 2000-step scan
__device__ float g_ln  [B_ * T_  * HH_];   // layernorm output
__device__ float g_scale[HH_];
__device__ float g_bias [HH_];
// tagged-value mailbox: [parity][group][slot]; slot = ci*64 + bb*32 + j
// packet = (tag:u32 << 32) | f32 bits of h. Double-buffered by step parity.
__device__ __align__(16) unsigned long long g_mail[2][8][1024];

// ---------------- packed fp32x2 FMA ----------------
__device__ __forceinline__ float2 ffma2(float2 a, float2 b, float2 c) {
    float2 d;
    asm("fma.rn.f32x2 %0, %1, %2, %3;"
        : "=l"(reinterpret_cast<unsigned long long &>(d))
        : "l"(reinterpret_cast<unsigned long long &>(a)),
          "l"(reinterpret_cast<unsigned long long &>(b)),
          "l"(reinterpret_cast<unsigned long long &>(c)));
    return d;
}

// ---------------- prep: fold BN; zero mailbox ----------------
__global__ void prep_kernel(const float* __restrict__ bz, const float* __restrict__ bh,
                            const float* __restrict__ zg, const float* __restrict__ zb,
                            const float* __restrict__ zm, const float* __restrict__ zv,
                            const float* __restrict__ hg, const float* __restrict__ hb,
                            const float* __restrict__ hm, const float* __restrict__ hv) {
    int n = threadIdx.x;  // 1024 threads
    float sc, bi;
    if (n < 512) {
        sc = zg[n] * rsqrtf(zv[n] + 1e-5f);
        bi = (bz[n] - zm[n]) * sc + zb[n];
    } else {
        int j = n - 512;
        sc = hg[j] * rsqrtf(hv[j] + 1e-5f);
        bi = (bh[j] - hm[j]) * sc + hb[j];
    }
    g_scale[n] = sc;
    g_bias[n]  = bi;
    unsigned long long* mp = &g_mail[0][0][0];
    for (int i = n; i < 2 * 8 * 1024; i += 1024) mp[i] = 0ull;
}

// ---------------- dummy: shifts ncu capture index onto scan_kernel ----------------
__global__ void dummy_kernel() {}

// ---------------- phase 1: wzh = BN(x_cat @ [Wz;Wh]^T + b) ----------------
__global__ __launch_bounds__(256) void gemm_wzh(const float* __restrict__ x,
                                                const float* __restrict__ Wz,
                                                const float* __restrict__ Wh) {
    __shared__ __align__(16) float As[32][68];
    __shared__ __align__(16) float Bs[32][68];
    int tid = threadIdx.x;
    int tx = tid & 15, ty = tid >> 4;
    int m0 = blockIdx.y * 64, n0 = blockIdx.x * 64;

    float2 acc[4][2];
#pragma unroll
    for (int i = 0; i < 4; i++) { acc[i][0] = make_float2(0.f, 0.f); acc[i][1] = make_float2(0.f, 0.f); }

    for (int k0 = 0; k0 < 512; k0 += 32) {
#pragma unroll
        for (int u = 0; u < 2; u++) {
            int v  = tid * 2 + u;
            int mm = v >> 3;
            int k4 = (v & 7) * 4;

            int m = m0 + mm;
            int b = m / TT_;
            int tp = m - b * TT_;
            const float* arow = (tp < T_) ? (x + ((size_t)(b * T_ + tp) << 9))
                                          : (x + ((size_t)((15 - b) * T_ + (tp - T_)) << 9));
            float4 av = *(const float4*)(arow + k0 + k4);
            As[k4 + 0][mm] = av.x; As[k4 + 1][mm] = av.y; As[k4 + 2][mm] = av.z; As[k4 + 3][mm] = av.w;

            int n = n0 + mm;
            const float* brow = (n < 512) ? (Wz + ((size_t)n << 9))
                                          : (Wh + ((size_t)(n - 512) << 9));
            float4 bv = *(const float4*)(brow + k0 + k4);
            Bs[k4 + 0][mm] = bv.x; Bs[k4 + 1][mm] = bv.y; Bs[k4 + 2][mm] = bv.z; Bs[k4 + 3][mm] = bv.w;
        }
        __syncthreads();
#pragma unroll
        for (int k = 0; k < 32; k++) {
            float4 a4 = *(const float4*)&As[k][ty * 4];
            float4 b4 = *(const float4*)&Bs[k][tx * 4];
            float2 b20 = make_float2(b4.x, b4.y), b21 = make_float2(b4.z, b4.w);
            float av[4] = {a4.x, a4.y, a4.z, a4.w};
#pragma unroll
            for (int i = 0; i < 4; i++) {
                float2 ad = make_float2(av[i], av[i]);
                acc[i][0] = ffma2(ad, b20, acc[i][0]);
                acc[i][1] = ffma2(ad, b21, acc[i][1]);
            }
        }
        __syncthreads();
    }
#pragma unroll
    for (int i = 0; i < 4; i++) {
        int m = m0 + ty * 4 + i;
        float* orow = g_wzh + (size_t)m * HH_ + n0 + tx * 4;
        int n = n0 + tx * 4;
        orow[0] = acc[i][0].x * g_scale[n + 0] + g_bias[n + 0];
        orow[1] = acc[i][0].y * g_scale[n + 1] + g_bias[n + 1];
        orow[2] = acc[i][1].x * g_scale[n + 2] + g_bias[n + 2];
        orow[3] = acc[i][1].y * g_scale[n + 3] + g_bias[n + 3];
    }
}

// ---------------- phase 2: persistent scan (relaxed tagged-mailbox, 16B polls) ----------------
// 128 CTAs = 8 groups x 16 CTAs. Group g owns batches {2g, 2g+1}.
// CTA ci holds U rows [32ci,+32) (z) and [512+32ci,+32) (h) in registers.
// Exchange: gate thread packs {tag=s+1, h} into one u64 (tag+value in the same
// single-copy-atomic word -> no fences needed), st.relaxed to mailbox; every
// thread polls 2 adjacent packets with ONE 16B v2.u64 relaxed load.
__global__ __launch_bounds__(512, 1) void scan_kernel(const float* __restrict__ U) {
    __shared__ __align__(16) float h_sm[2][512];
    __shared__ float red[2][8][64];

    int t   = threadIdx.x;
    int grp = blockIdx.x >> 4;
    int ci  = blockIdx.x & 15;
    int b0  = grp * 2;

    int r = t & 63;              // local row 0..63 (0..31 z, 32..63 h)
    int c = t >> 6;              // k-chunk 0..7 (64 k each)
    int urow = (r < 32) ? (ci * 32 + r) : (512 + ci * 32 + (r - 32));

    const float2* Up = (const float2*)(U + (size_t)urow * 512 + c * 64);
    float2 Ureg[32];
#pragma unroll
    for (int q = 0; q < 32; q++) Ureg[q] = __ldg(&Up[q]);

    for (int idx = t; idx < 1024; idx += 512) ((float*)h_sm)[idx] = 0.f;

    int bb = t >> 5, j = t & 31;           // gate threads: t < 64
    int bcur = b0 + bb;
    int cz = ci * 32 + j, ch = 512 + ci * 32 + j;
    float nz = 0.f, nh = 0.f;
    if (t < 64) {
        nz = __ldg(&g_wzh[(size_t)bcur * TT_ * HH_ + cz]);
        nh = __ldg(&g_wzh[(size_t)bcur * TT_ * HH_ + ch]);
    }
    // poll mapping: thread t polls slots 2t, 2t+1 (one 16B load).
    // slot = ci*64 + bb*32 + j  ->  batch dbb, h index hbase (= ci*32+j), hbase+1
    int ds    = 2 * t;
    int dbb   = (ds >> 5) & 1;
    int hbase = ((ds >> 6) << 5) | (ds & 31);
    __syncthreads();

    for (int s = 0; s < TT_; s++) {
        // matvec over this thread's 64-k chunk, both batches (float4 LDS broadcasts)
        float2 a0 = make_float2(0.f, 0.f), a1 = make_float2(0.f, 0.f);
        {
            const float4* h0 = (const float4*)&h_sm[0][c * 64];
            const float4* h1 = (const float4*)&h_sm[1][c * 64];
#pragma unroll
            for (int q = 0; q < 16; q++) {
                float4 v0 = h0[q];
                float4 v1 = h1[q];
                a0 = ffma2(Ureg[2 * q],     make_float2(v0.x, v0.y), a0);
                a0 = ffma2(Ureg[2 * q + 1], make_float2(v0.z, v0.w), a0);
                a1 = ffma2(Ureg[2 * q],     make_float2(v1.x, v1.y), a1);
                a1 = ffma2(Ureg[2 * q + 1], make_float2(v1.z, v1.w), a1);
            }
        }
        red[0][c][r] = a0.x + a0.y;
        red[1][c][r] = a1.x + a1.y;
        __syncthreads();   // matvec reads + red writes complete

        unsigned tag = (unsigned)(s + 1);
        int par = (s + 1) & 1;

        if (t < 64) {
            float uz = 0.f, uh = 0.f;
#pragma unroll
            for (int cc = 0; cc < 8; cc++) { uz += red[bb][cc][j]; uh += red[bb][cc][32 + j]; }
            float zt = __fdividef(1.f, 1.f + __expf(-(nz + uz)));
            float hc = fmaxf(nh + uh, 0.f);
            float hp = h_sm[bb][ci * 32 + j];
            float hn = zt * hp + (1.f - zt) * hc;
            __stcg(&g_hseq[((size_t)bcur * TT_ + s) * H_ + ci * 32 + j], hn);
            if (s + 1 < TT_) {
                unsigned long long pkt =
                    ((unsigned long long)tag << 32) | (unsigned long long)__float_as_uint(hn);
                asm volatile("st.relaxed.gpu.u64 [%0], %1;"
                             :: "l"(&g_mail[par][grp][ci * 64 + t]), "l"(pkt) : "memory");
                nz = __ldg(&g_wzh[((size_t)bcur * TT_ + s + 1) * HH_ + cz]);
                nh = __ldg(&g_wzh[((size_t)bcur * TT_ + s + 1) * HH_ + ch]);
            }
        }

        if (s + 1 < TT_) {
            // poll both packets with one 16B relaxed load; tag-match == data valid
            const unsigned long long* p = &g_mail[par][grp][ds];
            unsigned long long v0, v1;
            do {
                asm volatile("ld.relaxed.gpu.v2.u64 {%0, %1}, [%2];"
                             : "=l"(v0), "=l"(v1) : "l"(p) : "memory");
            } while (((unsigned)(v0 >> 32) < tag) || ((unsigned)(v1 >> 32) < tag));
            h_sm[dbb][hbase]     = __uint_as_float((unsigned)v0);
            h_sm[dbb][hbase + 1] = __uint_as_float((unsigned)v1);
            __syncthreads();   // all h_sm updates visible before next matvec
        }
    }
}

// ---------------- phase 3: LayerNorm ----------------
__global__ __launch_bounds__(256) void ln_kernel(const float* __restrict__ lng,
                                                 const float* __restrict__ lnb) {
    __shared__ float s_sum[8], s_sq[8];
    int row = blockIdx.x;
    int b = row / T_, tt = row - b * T_;
    int tid = threadIdx.x;
    int d = tid * 4;
    const float* base = (d < 512)
        ? (g_hseq + ((size_t)b * TT_ + tt) * H_ + d)
        : (g_hseq + ((size_t)(15 - b) * TT_ + T_ + tt) * H_ + (d - 512));
    float4 v = *(const float4*)base;
    float s = v.x + v.y + v.z + v.w;
    float q = v.x * v.x + v.y * v.y + v.z * v.z + v.w * v.w;
#pragma unroll
    for (int o = 16; o > 0; o >>= 1) {
        s += __shfl_down_sync(0xffffffffu, s, o);
        q += __shfl_down_sync(0xffffffffu, q, o);
    }
    int wid = tid >> 5, lid = tid & 31;
    if (lid == 0) { s_sum[wid] = s; s_sq[wid] = q; }
    __syncthreads();
    if (tid == 0) {
        float S = 0.f, Q = 0.f;
#pragma unroll
        for (int w = 0; w < 8; w++) { S += s_sum[w]; Q += s_sq[w]; }
        s_sum[0] = S; s_sq[0] = Q;
    }
    __syncthreads();
    float mu  = s_sum[0] * (1.f / 1024.f);
    float var = s_sq[0] * (1.f / 1024.f) - mu * mu;
    float inv = rsqrtf(var + 1e-5f);
    float4 g4 = *(const float4*)(lng + d);
    float4 b4 = *(const float4*)(lnb + d);
    float4 o;
    o.x = (v.x - mu) * inv * g4.x + b4.x;
    o.y = (v.y - mu) * inv * g4.y + b4.y;
    o.z = (v.z - mu) * inv * g4.z + b4.z;
    o.w = (v.w - mu) * inv * g4.w + b4.w;
    *(float4*)(g_ln + (size_t)row * HH_ + d) = o;
}

// ---------------- phase 4: out = tanh(ln @ pj_W^T + pj_b) ----------------
__global__ __launch_bounds__(256) void gemm_proj(const float* __restrict__ pjW,
                                                 const float* __restrict__ pjb,
                                                 float* __restrict__ out) {
    __shared__ __align__(16) float As[32][68];
    __shared__ __align__(16) float Bs[32][68];
    int tid = threadIdx.x;
    int tx = tid & 15, ty = tid >> 4;
    int m0 = blockIdx.y * 64, n0 = blockIdx.x * 64;

    float2 acc[4][2];
#pragma unroll
    for (int i = 0; i < 4; i++) { acc[i][0] = make_float2(0.f, 0.f); acc[i][1] = make_float2(0.f, 0.f); }

    for (int k0 = 0; k0 < 1024; k0 += 32) {
#pragma unroll
        for (int u = 0; u < 2; u++) {
            int v  = tid * 2 + u;
            int mm = v >> 3;
            int k4 = (v & 7) * 4;
            float4 av = *(const float4*)(g_ln + (size_t)(m0 + mm) * HH_ + k0 + k4);
            As[k4 + 0][mm] = av.x; As[k4 + 1][mm] = av.y; As[k4 + 2][mm] = av.z; As[k4 + 3][mm] = av.w;
            float4 bv = *(const float4*)(pjW + (size_t)(n0 + mm) * HH_ + k0 + k4);
            Bs[k4 + 0][mm] = bv.x; Bs[k4 + 1][mm] = bv.y; Bs[k4 + 2][mm] = bv.z; Bs[k4 + 3][mm] = bv.w;
        }
        __syncthreads();
#pragma unroll
        for (int k = 0; k < 32; k++) {
            float4 a4 = *(const float4*)&As[k][ty * 4];
            float4 b4 = *(const float4*)&Bs[k][tx * 4];
            float2 b20 = make_float2(b4.x, b4.y), b21 = make_float2(b4.z, b4.w);
            float av[4] = {a4.x, a4.y, a4.z, a4.w};
#pragma unroll
            for (int i = 0; i < 4; i++) {
                float2 ad = make_float2(av[i], av[i]);
                acc[i][0] = ffma2(ad, b20, acc[i][0]);
                acc[i][1] = ffma2(ad, b21, acc[i][1]);
            }
        }
        __syncthreads();
    }
#pragma unroll
    for (int i = 0; i < 4; i++) {
        int m = m0 + ty * 4 + i;
        int n = n0 + tx * 4;
        float* orow = out + (size_t)m * HH_ + n;
        orow[0] = tanhf(acc[i][0].x + pjb[n + 0]);
        orow[1] = tanhf(acc[i][0].y + pjb[n + 1]);
        orow[2] = tanhf(acc[i][1].x + pjb[n + 2]);
        orow[3] = tanhf(acc[i][1].y + pjb[n + 3]);
    }
}

// ---------------- tail: x_len pass-through ----------------
__global__ void tail_kernel(const int* __restrict__ xlen, float* __restrict__ out) {
    int t = threadIdx.x;
    if (t < B_) out[(size_t)B_ * T_ * HH_ + t] = (float)xlen[t];
}

extern "C" void kernel_launch(void* const* d_in, const int* in_sizes, int n_in,
                              void* d_out, int out_size) {
    const float* x   = (const float*)d_in[0];
    const int*   xl  = (const int*)  d_in[1];
    const float* Wz  = (const float*)d_in[2];
    const float* bz  = (const float*)d_in[3];
    const float* Wh  = (const float*)d_in[4];
    const float* bh  = (const float*)d_in[5];
    const float* U   = (const float*)d_in[6];
    const float* zg  = (const float*)d_in[7];
    const float* zb  = (const float*)d_in[8];
    const float* zm  = (const float*)d_in[9];
    const float* zv  = (const float*)d_in[10];
    const float* hg  = (const float*)d_in[11];
    const float* hb  = (const float*)d_in[12];
    const float* hm  = (const float*)d_in[13];
    const float* hv  = (const float*)d_in[14];
    const float* lng = (const float*)d_in[15];
    const float* lnb = (const float*)d_in[16];
    const float* pjW = (const float*)d_in[17];
    const float* pjb = (const float*)d_in[18];
    float* out = (float*)d_out;

    prep_kernel<<<1, 1024>>>(bz, bh, zg, zb, zm, zv, hg, hb, hm, hv);
    gemm_wzh<<<dim3(16, 500), 256>>>(x, Wz, Wh);
    dummy_kernel<<<1, 32>>>();            // shifts ncu capture onto scan_kernel
    scan_kernel<<<128, 512>>>(U);
    ln_kernel<<<16000, 256>>>(lng, lnb);
    gemm_proj<<<dim3(16, 250), 256>>>(pjW, pjb, out);
    if (out_size >= B_ * T_ * HH_ + B_) {
        tail_kernel<<<1, 32>>>(xl, out);
    }
    (void)in_sizes; (void)n_in;
}

// round 8
// speedup vs baseline: 2.0181x; 1.1485x over previous
#include <cuda_runtime.h>
#include <math.h>
#include <stdint.h>

// Problem constants (fixed shapes)
#define B_  16
#define T_  1000
#define TT_ 2000
#define F_  512
#define H_  512
#define HH_ 1024

// ---------------- device scratch ----------------
__device__ float g_wzh [B_ * TT_ * HH_];   // BN'd pre-activations
__device__ float g_hseq[B_ * TT_ * H_ ];   // hidden states over the 2000-step scan
__device__ float g_ln  [B_ * T_  * HH_];   // layernorm output
__device__ float g_scale[HH_];
__device__ float g_bias [HH_];
// tagged-value mailbox: [parity][group][slot]; slot = ci*64 + bb*32 + j
// packet = (tag:u32 << 32) | f32 bits of h. Double-buffered by step parity.
__device__ __align__(16) unsigned long long g_mail[2][8][1024];

// ---------------- packed fp32x2 FMA ----------------
__device__ __forceinline__ float2 ffma2(float2 a, float2 b, float2 c) {
    float2 d;
    asm("fma.rn.f32x2 %0, %1, %2, %3;"
        : "=l"(reinterpret_cast<unsigned long long &>(d))
        : "l"(reinterpret_cast<unsigned long long &>(a)),
          "l"(reinterpret_cast<unsigned long long &>(b)),
          "l"(reinterpret_cast<unsigned long long &>(c)));
    return d;
}

// ---------------- prep: fold BN; zero mailbox ----------------
__global__ void prep_kernel(const float* __restrict__ bz, const float* __restrict__ bh,
                            const float* __restrict__ zg, const float* __restrict__ zb,
                            const float* __restrict__ zm, const float* __restrict__ zv,
                            const float* __restrict__ hg, const float* __restrict__ hb,
                            const float* __restrict__ hm, const float* __restrict__ hv) {
    int n = threadIdx.x;  // 1024 threads
    float sc, bi;
    if (n < 512) {
        sc = zg[n] * rsqrtf(zv[n] + 1e-5f);
        bi = (bz[n] - zm[n]) * sc + zb[n];
    } else {
        int j = n - 512;
        sc = hg[j] * rsqrtf(hv[j] + 1e-5f);
        bi = (bh[j] - hm[j]) * sc + hb[j];
    }
    g_scale[n] = sc;
    g_bias[n]  = bi;
    unsigned long long* mp = &g_mail[0][0][0];
    for (int i = n; i < 2 * 8 * 1024; i += 1024) mp[i] = 0ull;
}

// ---------------- dummy: keeps ncu capture index on the scan kernel ----------------
__global__ void dummy_kernel() {}

// ---------------- phase 1: wzh = BN(x_cat @ [Wz;Wh]^T + b) ----------------
__global__ __launch_bounds__(256) void gemm_wzh(const float* __restrict__ x,
                                                const float* __restrict__ Wz,
                                                const float* __restrict__ Wh) {
    __shared__ __align__(16) float As[32][68];
    __shared__ __align__(16) float Bs[32][68];
    int tid = threadIdx.x;
    int tx = tid & 15, ty = tid >> 4;
    int m0 = blockIdx.y * 64, n0 = blockIdx.x * 64;

    float2 acc[4][2];
#pragma unroll
    for (int i = 0; i < 4; i++) { acc[i][0] = make_float2(0.f, 0.f); acc[i][1] = make_float2(0.f, 0.f); }

    for (int k0 = 0; k0 < 512; k0 += 32) {
#pragma unroll
        for (int u = 0; u < 2; u++) {
            int v  = tid * 2 + u;
            int mm = v >> 3;
            int k4 = (v & 7) * 4;

            int m = m0 + mm;
            int b = m / TT_;
            int tp = m - b * TT_;
            const float* arow = (tp < T_) ? (x + ((size_t)(b * T_ + tp) << 9))
                                          : (x + ((size_t)((15 - b) * T_ + (tp - T_)) << 9));
            float4 av = *(const float4*)(arow + k0 + k4);
            As[k4 + 0][mm] = av.x; As[k4 + 1][mm] = av.y; As[k4 + 2][mm] = av.z; As[k4 + 3][mm] = av.w;

            int n = n0 + mm;
            const float* brow = (n < 512) ? (Wz + ((size_t)n << 9))
                                          : (Wh + ((size_t)(n - 512) << 9));
            float4 bv = *(const float4*)(brow + k0 + k4);
            Bs[k4 + 0][mm] = bv.x; Bs[k4 + 1][mm] = bv.y; Bs[k4 + 2][mm] = bv.z; Bs[k4 + 3][mm] = bv.w;
        }
        __syncthreads();
#pragma unroll
        for (int k = 0; k < 32; k++) {
            float4 a4 = *(const float4*)&As[k][ty * 4];
            float4 b4 = *(const float4*)&Bs[k][tx * 4];
            float2 b20 = make_float2(b4.x, b4.y), b21 = make_float2(b4.z, b4.w);
            float av[4] = {a4.x, a4.y, a4.z, a4.w};
#pragma unroll
            for (int i = 0; i < 4; i++) {
                float2 ad = make_float2(av[i], av[i]);
                acc[i][0] = ffma2(ad, b20, acc[i][0]);
                acc[i][1] = ffma2(ad, b21, acc[i][1]);
            }
        }
        __syncthreads();
    }
#pragma unroll
    for (int i = 0; i < 4; i++) {
        int m = m0 + ty * 4 + i;
        float* orow = g_wzh + (size_t)m * HH_ + n0 + tx * 4;
        int n = n0 + tx * 4;
        orow[0] = acc[i][0].x * g_scale[n + 0] + g_bias[n + 0];
        orow[1] = acc[i][0].y * g_scale[n + 1] + g_bias[n + 1];
        orow[2] = acc[i][1].x * g_scale[n + 2] + g_bias[n + 2];
        orow[3] = acc[i][1].y * g_scale[n + 3] + g_bias[n + 3];
    }
}

// ---------------- phase 2: persistent scan, chunk-specialized mailbox polling ----------------
// 128 CTAs = 8 groups x 16 CTAs. Group g owns batches {2g, 2g+1}.
// CTA ci holds U rows [32ci,+32) (z) and [512+32ci,+32) (h) in registers.
// Per step: chunk-c threads (t>>6==c) poll ONLY slots [c*128, c*128+128)
// (producers 2c, 2c+1, both batches), stage into their h_sm region, pass a
// 64-thread named barrier, matvec, then ONE CTA-wide sync before gates.
// red[] double-buffered by parity; gate h_prev kept in a register.
__global__ __launch_bounds__(512, 1) void scan_kernel(const float* __restrict__ U) {
    __shared__ __align__(16) float h_sm[2][512];
    __shared__ float red[2][2][8][64];   // [parity][batch][chunk][row]

    int t   = threadIdx.x;
    int grp = blockIdx.x >> 4;
    int ci  = blockIdx.x & 15;
    int b0  = grp * 2;

    int r = t & 63;              // local row 0..63 (0..31 z, 32..63 h)
    int c = t >> 6;              // k-chunk 0..7 (64 k each)
    int urow = (r < 32) ? (ci * 32 + r) : (512 + ci * 32 + (r - 32));

    const float2* Up = (const float2*)(U + (size_t)urow * 512 + c * 64);
    float2 Ureg[32];
#pragma unroll
    for (int q = 0; q < 32; q++) Ureg[q] = __ldg(&Up[q]);

    for (int idx = t; idx < 1024; idx += 512) ((float*)h_sm)[idx] = 0.f;

    int bb = t >> 5, j = t & 31;           // gate threads: t < 64
    int bcur = b0 + bb;
    int cz = ci * 32 + j, ch = 512 + ci * 32 + j;
    float nz = 0.f, nh = 0.f;
    float hp = 0.f;                        // gate thread's own previous h (register)
    if (t < 64) {
        nz = __ldg(&g_wzh[(size_t)bcur * TT_ * HH_ + cz]);
        nh = __ldg(&g_wzh[(size_t)bcur * TT_ * HH_ + ch]);
    }
    // chunk-specialized poll mapping: this thread polls slots ds, ds+1 where
    // ds = c*128 + 2*(t&63)  -> only packets this chunk's matvec needs.
    int ds    = c * 128 + 2 * (t & 63);
    int dbb   = (ds >> 5) & 1;
    int hbase = ((ds >> 6) << 5) | (ds & 31);
    __syncthreads();

    for (int s = 0; s < TT_; s++) {
        int par2 = s & 1;
        // matvec over this thread's 64-k chunk, both batches (float4 LDS broadcasts)
        float2 a0 = make_float2(0.f, 0.f), a1 = make_float2(0.f, 0.f);
        {
            const float4* h0 = (const float4*)&h_sm[0][c * 64];
            const float4* h1 = (const float4*)&h_sm[1][c * 64];
#pragma unroll
            for (int q = 0; q < 16; q++) {
                float4 v0 = h0[q];
                float4 v1 = h1[q];
                a0 = ffma2(Ureg[2 * q],     make_float2(v0.x, v0.y), a0);
                a0 = ffma2(Ureg[2 * q + 1], make_float2(v0.z, v0.w), a0);
                a1 = ffma2(Ureg[2 * q],     make_float2(v1.x, v1.y), a1);
                a1 = ffma2(Ureg[2 * q + 1], make_float2(v1.z, v1.w), a1);
            }
        }
        red[par2][0][c][r] = a0.x + a0.y;
        red[par2][1][c][r] = a1.x + a1.y;
        __syncthreads();   // all chunks' red ready for gates; h_sm reads complete

        unsigned tag = (unsigned)(s + 1);
        int par = (s + 1) & 1;

        if (t < 64) {
            float uz = 0.f, uh = 0.f;
#pragma unroll
            for (int cc = 0; cc < 8; cc++) {
                uz += red[par2][bb][cc][j];
                uh += red[par2][bb][cc][32 + j];
            }
            float zt = __fdividef(1.f, 1.f + __expf(-(nz + uz)));
            float hc = fmaxf(nh + uh, 0.f);
            float hn = zt * hp + (1.f - zt) * hc;
            hp = hn;
            __stcg(&g_hseq[((size_t)bcur * TT_ + s) * H_ + ci * 32 + j], hn);
            if (s + 1 < TT_) {
                unsigned long long pkt =
                    ((unsigned long long)tag << 32) | (unsigned long long)__float_as_uint(hn);
                asm volatile("st.relaxed.gpu.u64 [%0], %1;"
                             :: "l"(&g_mail[par][grp][ci * 64 + t]), "l"(pkt) : "memory");
                nz = __ldg(&g_wzh[((size_t)bcur * TT_ + s + 1) * HH_ + cz]);
                nh = __ldg(&g_wzh[((size_t)bcur * TT_ + s + 1) * HH_ + ch]);
            }
        }

        if (s + 1 < TT_) {
            // poll ONLY this chunk's 2 packets (producers 2c, 2c+1)
            const unsigned long long* p = &g_mail[par][grp][ds];
            unsigned long long v0, v1;
            do {
                asm volatile("ld.relaxed.gpu.v2.u64 {%0, %1}, [%2];"
                             : "=l"(v0), "=l"(v1) : "l"(p) : "memory");
            } while (((unsigned)(v0 >> 32) < tag) || ((unsigned)(v1 >> 32) < tag));
            h_sm[dbb][hbase]     = __uint_as_float((unsigned)v0);
            h_sm[dbb][hbase + 1] = __uint_as_float((unsigned)v1);
            // 64-thread named barrier: this chunk's h_sm region complete
            asm volatile("bar.sync %0, %1;" :: "r"(c + 1), "r"(64) : "memory");
        }
    }
}

// ---------------- phase 3: LayerNorm ----------------
__global__ __launch_bounds__(256) void ln_kernel(const float* __restrict__ lng,
                                                 const float* __restrict__ lnb) {
    __shared__ float s_sum[8], s_sq[8];
    int row = blockIdx.x;
    int b = row / T_, tt = row - b * T_;
    int tid = threadIdx.x;
    int d = tid * 4;
    const float* base = (d < 512)
        ? (g_hseq + ((size_t)b * TT_ + tt) * H_ + d)
        : (g_hseq + ((size_t)(15 - b) * TT_ + T_ + tt) * H_ + (d - 512));
    float4 v = *(const float4*)base;
    float s = v.x + v.y + v.z + v.w;
    float q = v.x * v.x + v.y * v.y + v.z * v.z + v.w * v.w;
#pragma unroll
    for (int o = 16; o > 0; o >>= 1) {
        s += __shfl_down_sync(0xffffffffu, s, o);
        q += __shfl_down_sync(0xffffffffu, q, o);
    }
    int wid = tid >> 5, lid = tid & 31;
    if (lid == 0) { s_sum[wid] = s; s_sq[wid] = q; }
    __syncthreads();
    if (tid == 0) {
        float S = 0.f, Q = 0.f;
#pragma unroll
        for (int w = 0; w < 8; w++) { S += s_sum[w]; Q += s_sq[w]; }
        s_sum[0] = S; s_sq[0] = Q;
    }
    __syncthreads();
    float mu  = s_sum[0] * (1.f / 1024.f);
    float var = s_sq[0] * (1.f / 1024.f) - mu * mu;
    float inv = rsqrtf(var + 1e-5f);
    float4 g4 = *(const float4*)(lng + d);
    float4 b4 = *(const float4*)(lnb + d);
    float4 o;
    o.x = (v.x - mu) * inv * g4.x + b4.x;
    o.y = (v.y - mu) * inv * g4.y + b4.y;
    o.z = (v.z - mu) * inv * g4.z + b4.z;
    o.w = (v.w - mu) * inv * g4.w + b4.w;
    *(float4*)(g_ln + (size_t)row * HH_ + d) = o;
}

// ---------------- phase 4: out = tanh(ln @ pj_W^T + pj_b) ----------------
__global__ __launch_bounds__(256) void gemm_proj(const float* __restrict__ pjW,
                                                 const float* __restrict__ pjb,
                                                 float* __restrict__ out) {
    __shared__ __align__(16) float As[32][68];
    __shared__ __align__(16) float Bs[32][68];
    int tid = threadIdx.x;
    int tx = tid & 15, ty = tid >> 4;
    int m0 = blockIdx.y * 64, n0 = blockIdx.x * 64;

    float2 acc[4][2];
#pragma unroll
    for (int i = 0; i < 4; i++) { acc[i][0] = make_float2(0.f, 0.f); acc[i][1] = make_float2(0.f, 0.f); }

    for (int k0 = 0; k0 < 1024; k0 += 32) {
#pragma unroll
        for (int u = 0; u < 2; u++) {
            int v  = tid * 2 + u;
            int mm = v >> 3;
            int k4 = (v & 7) * 4;
            float4 av = *(const float4*)(g_ln + (size_t)(m0 + mm) * HH_ + k0 + k4);
            As[k4 + 0][mm] = av.x; As[k4 + 1][mm] = av.y; As[k4 + 2][mm] = av.z; As[k4 + 3][mm] = av.w;
            float4 bv = *(const float4*)(pjW + (size_t)(n0 + mm) * HH_ + k0 + k4);
            Bs[k4 + 0][mm] = bv.x; Bs[k4 + 1][mm] = bv.y; Bs[k4 + 2][mm] = bv.z; Bs[k4 + 3][mm] = bv.w;
        }
        __syncthreads();
#pragma unroll
        for (int k = 0; k < 32; k++) {
            float4 a4 = *(const float4*)&As[k][ty * 4];
            float4 b4 = *(const float4*)&Bs[k][tx * 4];
            float2 b20 = make_float2(b4.x, b4.y), b21 = make_float2(b4.z, b4.w);
            float av[4] = {a4.x, a4.y, a4.z, a4.w};
#pragma unroll
            for (int i = 0; i < 4; i++) {
                float2 ad = make_float2(av[i], av[i]);
                acc[i][0] = ffma2(ad, b20, acc[i][0]);
                acc[i][1] = ffma2(ad, b21, acc[i][1]);
            }
        }
        __syncthreads();
    }
#pragma unroll
    for (int i = 0; i < 4; i++) {
        int m = m0 + ty * 4 + i;
        int n = n0 + tx * 4;
        float* orow = out + (size_t)m * HH_ + n;
        orow[0] = tanhf(acc[i][0].x + pjb[n + 0]);
        orow[1] = tanhf(acc[i][0].y + pjb[n + 1]);
        orow[2] = tanhf(acc[i][1].x + pjb[n + 2]);
        orow[3] = tanhf(acc[i][1].y + pjb[n + 3]);
    }
}

// ---------------- tail: x_len pass-through ----------------
__global__ void tail_kernel(const int* __restrict__ xlen, float* __restrict__ out) {
    int t = threadIdx.x;
    if (t < B_) out[(size_t)B_ * T_ * HH_ + t] = (float)xlen[t];
}

extern "C" void kernel_launch(void* const* d_in, const int* in_sizes, int n_in,
                              void* d_out, int out_size) {
    const float* x   = (const float*)d_in[0];
    const int*   xl  = (const int*)  d_in[1];
    const float* Wz  = (const float*)d_in[2];
    const float* bz  = (const float*)d_in[3];
    const float* Wh  = (const float*)d_in[4];
    const float* bh  = (const float*)d_in[5];
    const float* U   = (const float*)d_in[6];
    const float* zg  = (const float*)d_in[7];
    const float* zb  = (const float*)d_in[8];
    const float* zm  = (const float*)d_in[9];
    const float* zv  = (const float*)d_in[10];
    const float* hg  = (const float*)d_in[11];
    const float* hb  = (const float*)d_in[12];
    const float* hm  = (const float*)d_in[13];
    const float* hv  = (const float*)d_in[14];
    const float* lng = (const float*)d_in[15];
    const float* lnb = (const float*)d_in[16];
    const float* pjW = (const float*)d_in[17];
    const float* pjb = (const float*)d_in[18];
    float* out = (float*)d_out;

    prep_kernel<<<1, 1024>>>(bz, bh, zg, zb, zm, zv, hg, hb, hm, hv);
    gemm_wzh<<<dim3(16, 500), 256>>>(x, Wz, Wh);
    dummy_kernel<<<1, 32>>>();            // keeps ncu capture on scan_kernel
    scan_kernel<<<128, 512>>>(U);
    ln_kernel<<<16000, 256>>>(lng, lnb);
    gemm_proj<<<dim3(16, 250), 256>>>(pjW, pjb, out);
    if (out_size >= B_ * T_ * HH_ + B_) {
        tail_kernel<<<1, 32>>>(xl, out);
    }
    (void)in_sizes; (void)n_in;
}

// round 9
// speedup vs baseline: 2.3486x; 1.1638x over previous
#include <cuda_runtime.h>
#include <math.h>
#include <stdint.h>
#include <mma.h>

using namespace nvcuda;

// Problem constants (fixed shapes)
#define B_  16
#define T_  1000
#define TT_ 2000
#define F_  512
#define H_  512
#define HH_ 1024

// ---------------- device scratch ----------------
__device__ float g_wzh [B_ * TT_ * HH_];   // BN'd pre-activations
__device__ float g_hseq[B_ * TT_ * H_ ];   // hidden states over the 2000-step scan
__device__ float g_ln  [B_ * T_  * HH_];   // layernorm output
__device__ float g_scale[HH_];
__device__ float g_bias [HH_];
// tagged-value mailbox: [parity][group][slot]; packet = (tag<<32)|f32
__device__ __align__(16) unsigned long long g_mail[2][8][1024];

// ---------------- packed fp32x2 FMA ----------------
__device__ __forceinline__ float2 ffma2(float2 a, float2 b, float2 c) {
    float2 d;
    asm("fma.rn.f32x2 %0, %1, %2, %3;"
        : "=l"(reinterpret_cast<unsigned long long &>(d))
        : "l"(reinterpret_cast<unsigned long long &>(a)),
          "l"(reinterpret_cast<unsigned long long &>(b)),
          "l"(reinterpret_cast<unsigned long long &>(c)));
    return d;
}

// ---------------- prep: fold BN; zero mailbox ----------------
__global__ void prep_kernel(const float* __restrict__ bz, const float* __restrict__ bh,
                            const float* __restrict__ zg, const float* __restrict__ zb,
                            const float* __restrict__ zm, const float* __restrict__ zv,
                            const float* __restrict__ hg, const float* __restrict__ hb,
                            const float* __restrict__ hm, const float* __restrict__ hv) {
    int n = threadIdx.x;  // 1024 threads
    float sc, bi;
    if (n < 512) {
        sc = zg[n] * rsqrtf(zv[n] + 1e-5f);
        bi = (bz[n] - zm[n]) * sc + zb[n];
    } else {
        int j = n - 512;
        sc = hg[j] * rsqrtf(hv[j] + 1e-5f);
        bi = (bh[j] - hm[j]) * sc + hb[j];
    }
    g_scale[n] = sc;
    g_bias[n]  = bi;
    unsigned long long* mp = &g_mail[0][0][0];
    for (int i = n; i < 2 * 8 * 1024; i += 1024) mp[i] = 0ull;
}

// ---------------- dummy: keeps ncu capture index on the scan kernel ----------------
__global__ void dummy_kernel() {}

// ---------------- phase 1: wzh = BN(x_cat @ [Wz;Wh]^T + b), tf32 wmma ----------------
// Block tile 64x64, 8 warps (2 m x 4 n), warp tile 32x16. K staged 16 at a time.
__global__ __launch_bounds__(256) void gemm_wzh(const float* __restrict__ x,
                                                const float* __restrict__ Wz,
                                                const float* __restrict__ Wh) {
    __shared__ __align__(16) float As[64][24];   // A tile  (row-major, ld 24)
    __shared__ __align__(16) float Bs[16][72];   // B^T tile (k x n, ld 72)
    __shared__ __align__(16) float Cs[64][72];   // C tile for epilogue

    int tid = threadIdx.x;
    int wid = tid >> 5;
    int mw = (wid & 1) * 32;        // warp m offset
    int nw = (wid >> 1) * 16;       // warp n offset
    int m0 = blockIdx.y * 64, n0 = blockIdx.x * 64;

    wmma::fragment<wmma::accumulator, 16, 16, 8, float> c_frag[2];
    wmma::fill_fragment(c_frag[0], 0.f);
    wmma::fill_fragment(c_frag[1], 0.f);

    // per-thread load coords: one float4 of A and one float4 of B per stage
    int lrow = tid >> 2;            // 0..63
    int lk4  = (tid & 3) * 4;       // 0,4,8,12

    // A row pointer (x_cat gather with batch reversal), fixed per thread
    int m = m0 + lrow;
    int b = m / TT_;
    int tp = m - b * TT_;
    const float* arow = (tp < T_) ? (x + ((size_t)(b * T_ + tp) << 9))
                                  : (x + ((size_t)((15 - b) * T_ + (tp - T_)) << 9));
    int n = n0 + lrow;
    const float* brow = (n < 512) ? (Wz + ((size_t)n << 9))
                                  : (Wh + ((size_t)(n - 512) << 9));

    for (int k0 = 0; k0 < 512; k0 += 16) {
        float4 av = *(const float4*)(arow + k0 + lk4);
        *(float4*)&As[lrow][lk4] = av;
        float4 bv = *(const float4*)(brow + k0 + lk4);
        Bs[lk4 + 0][lrow] = bv.x; Bs[lk4 + 1][lrow] = bv.y;
        Bs[lk4 + 2][lrow] = bv.z; Bs[lk4 + 3][lrow] = bv.w;
        __syncthreads();
#pragma unroll
        for (int kk = 0; kk < 16; kk += 8) {
            wmma::fragment<wmma::matrix_b, 16, 16, 8, wmma::precision::tf32, wmma::row_major> b_frag;
            wmma::load_matrix_sync(b_frag, &Bs[kk][nw], 72);
#pragma unroll
            for (int i = 0; i < b_frag.num_elements; i++)
                b_frag.x[i] = wmma::__float_to_tf32(b_frag.x[i]);
#pragma unroll
            for (int i = 0; i < 2; i++) {
                wmma::fragment<wmma::matrix_a, 16, 16, 8, wmma::precision::tf32, wmma::row_major> a_frag;
                wmma::load_matrix_sync(a_frag, &As[mw + 16 * i][kk], 24);
#pragma unroll
                for (int e = 0; e < a_frag.num_elements; e++)
                    a_frag.x[e] = wmma::__float_to_tf32(a_frag.x[e]);
                wmma::mma_sync(c_frag[i], a_frag, b_frag, c_frag[i]);
            }
        }
        __syncthreads();
    }

    wmma::store_matrix_sync(&Cs[mw][nw], c_frag[0], 72, wmma::mem_row_major);
    wmma::store_matrix_sync(&Cs[mw + 16][nw], c_frag[1], 72, wmma::mem_row_major);
    __syncthreads();

    // epilogue: BN scale/bias, vectorized
    for (int e = tid; e < 1024; e += 256) {
        int row = e >> 4;
        int col = (e & 15) * 4;
        int nn = n0 + col;
        float4 cv = *(const float4*)&Cs[row][col];
        float4 o;
        o.x = cv.x * g_scale[nn + 0] + g_bias[nn + 0];
        o.y = cv.y * g_scale[nn + 1] + g_bias[nn + 1];
        o.z = cv.z * g_scale[nn + 2] + g_bias[nn + 2];
        o.w = cv.w * g_scale[nn + 3] + g_bias[nn + 3];
        *(float4*)(g_wzh + (size_t)(m0 + row) * HH_ + nn) = o;
    }
}

// ---------------- phase 2: persistent scan, chunk-specialized mailbox polling ----------------
__global__ __launch_bounds__(512, 1) void scan_kernel(const float* __restrict__ U) {
    __shared__ __align__(16) float h_sm[2][512];
    __shared__ float red[2][2][8][64];   // [parity][batch][chunk][row]

    int t   = threadIdx.x;
    int grp = blockIdx.x >> 4;
    int ci  = blockIdx.x & 15;
    int b0  = grp * 2;

    int r = t & 63;              // local row 0..63 (0..31 z, 32..63 h)
    int c = t >> 6;              // k-chunk 0..7 (64 k each)
    int urow = (r < 32) ? (ci * 32 + r) : (512 + ci * 32 + (r - 32));

    const float2* Up = (const float2*)(U + (size_t)urow * 512 + c * 64);
    float2 Ureg[32];
#pragma unroll
    for (int q = 0; q < 32; q++) Ureg[q] = __ldg(&Up[q]);

    for (int idx = t; idx < 1024; idx += 512) ((float*)h_sm)[idx] = 0.f;

    int bb = t >> 5, j = t & 31;           // gate threads: t < 64
    int bcur = b0 + bb;
    int cz = ci * 32 + j, ch = 512 + ci * 32 + j;
    float nz = 0.f, nh = 0.f;
    float hp = 0.f;                        // gate thread's own previous h (register)
    if (t < 64) {
        nz = __ldg(&g_wzh[(size_t)bcur * TT_ * HH_ + cz]);
        nh = __ldg(&g_wzh[(size_t)bcur * TT_ * HH_ + ch]);
    }
    int ds    = c * 128 + 2 * (t & 63);
    int dbb   = (ds >> 5) & 1;
    int hbase = ((ds >> 6) << 5) | (ds & 31);
    __syncthreads();

    for (int s = 0; s < TT_; s++) {
        int par2 = s & 1;
        float2 a0 = make_float2(0.f, 0.f), a1 = make_float2(0.f, 0.f);
        {
            const float4* h0 = (const float4*)&h_sm[0][c * 64];
            const float4* h1 = (const float4*)&h_sm[1][c * 64];
#pragma unroll
            for (int q = 0; q < 16; q++) {
                float4 v0 = h0[q];
                float4 v1 = h1[q];
                a0 = ffma2(Ureg[2 * q],     make_float2(v0.x, v0.y), a0);
                a0 = ffma2(Ureg[2 * q + 1], make_float2(v0.z, v0.w), a0);
                a1 = ffma2(Ureg[2 * q],     make_float2(v1.x, v1.y), a1);
                a1 = ffma2(Ureg[2 * q + 1], make_float2(v1.z, v1.w), a1);
            }
        }
        red[par2][0][c][r] = a0.x + a0.y;
        red[par2][1][c][r] = a1.x + a1.y;
        __syncthreads();

        unsigned tag = (unsigned)(s + 1);
        int par = (s + 1) & 1;

        if (t < 64) {
            float uz = 0.f, uh = 0.f;
#pragma unroll
            for (int cc = 0; cc < 8; cc++) {
                uz += red[par2][bb][cc][j];
                uh += red[par2][bb][cc][32 + j];
            }
            float zt = __fdividef(1.f, 1.f + __expf(-(nz + uz)));
            float hc = fmaxf(nh + uh, 0.f);
            float hn = zt * hp + (1.f - zt) * hc;
            hp = hn;
            __stcg(&g_hseq[((size_t)bcur * TT_ + s) * H_ + ci * 32 + j], hn);
            if (s + 1 < TT_) {
                unsigned long long pkt =
                    ((unsigned long long)tag << 32) | (unsigned long long)__float_as_uint(hn);
                asm volatile("st.relaxed.gpu.u64 [%0], %1;"
                             :: "l"(&g_mail[par][grp][ci * 64 + t]), "l"(pkt) : "memory");
                nz = __ldg(&g_wzh[((size_t)bcur * TT_ + s + 1) * HH_ + cz]);
                nh = __ldg(&g_wzh[((size_t)bcur * TT_ + s + 1) * HH_ + ch]);
            }
        }

        if (s + 1 < TT_) {
            const unsigned long long* p = &g_mail[par][grp][ds];
            unsigned long long v0, v1;
            do {
                asm volatile("ld.relaxed.gpu.v2.u64 {%0, %1}, [%2];"
                             : "=l"(v0), "=l"(v1) : "l"(p) : "memory");
            } while (((unsigned)(v0 >> 32) < tag) || ((unsigned)(v1 >> 32) < tag));
            h_sm[dbb][hbase]     = __uint_as_float((unsigned)v0);
            h_sm[dbb][hbase + 1] = __uint_as_float((unsigned)v1);
            asm volatile("bar.sync %0, %1;" :: "r"(c + 1), "r"(64) : "memory");
        }
    }
}

// ---------------- phase 3: LayerNorm ----------------
__global__ __launch_bounds__(256) void ln_kernel(const float* __restrict__ lng,
                                                 const float* __restrict__ lnb) {
    __shared__ float s_sum[8], s_sq[8];
    int row = blockIdx.x;
    int b = row / T_, tt = row - b * T_;
    int tid = threadIdx.x;
    int d = tid * 4;
    const float* base = (d < 512)
        ? (g_hseq + ((size_t)b * TT_ + tt) * H_ + d)
        : (g_hseq + ((size_t)(15 - b) * TT_ + T_ + tt) * H_ + (d - 512));
    float4 v = *(const float4*)base;
    float s = v.x + v.y + v.z + v.w;
    float q = v.x * v.x + v.y * v.y + v.z * v.z + v.w * v.w;
#pragma unroll
    for (int o = 16; o > 0; o >>= 1) {
        s += __shfl_down_sync(0xffffffffu, s, o);
        q += __shfl_down_sync(0xffffffffu, q, o);
    }
    int wid = tid >> 5, lid = tid & 31;
    if (lid == 0) { s_sum[wid] = s; s_sq[wid] = q; }
    __syncthreads();
    if (tid == 0) {
        float S = 0.f, Q = 0.f;
#pragma unroll
        for (int w = 0; w < 8; w++) { S += s_sum[w]; Q += s_sq[w]; }
        s_sum[0] = S; s_sq[0] = Q;
    }
    __syncthreads();
    float mu  = s_sum[0] * (1.f / 1024.f);
    float var = s_sq[0] * (1.f / 1024.f) - mu * mu;
    float inv = rsqrtf(var + 1e-5f);
    float4 g4 = *(const float4*)(lng + d);
    float4 b4 = *(const float4*)(lnb + d);
    float4 o;
    o.x = (v.x - mu) * inv * g4.x + b4.x;
    o.y = (v.y - mu) * inv * g4.y + b4.y;
    o.z = (v.z - mu) * inv * g4.z + b4.z;
    o.w = (v.w - mu) * inv * g4.w + b4.w;
    *(float4*)(g_ln + (size_t)row * HH_ + d) = o;
}

// ---------------- phase 4: out = tanh(ln @ pj_W^T + pj_b), tf32 wmma ----------------
__global__ __launch_bounds__(256) void gemm_proj(const float* __restrict__ pjW,
                                                 const float* __restrict__ pjb,
                                                 float* __restrict__ out) {
    __shared__ __align__(16) float As[64][24];
    __shared__ __align__(16) float Bs[16][72];
    __shared__ __align__(16) float Cs[64][72];

    int tid = threadIdx.x;
    int wid = tid >> 5;
    int mw = (wid & 1) * 32;
    int nw = (wid >> 1) * 16;
    int m0 = blockIdx.y * 64, n0 = blockIdx.x * 64;

    wmma::fragment<wmma::accumulator, 16, 16, 8, float> c_frag[2];
    wmma::fill_fragment(c_frag[0], 0.f);
    wmma::fill_fragment(c_frag[1], 0.f);

    int lrow = tid >> 2;
    int lk4  = (tid & 3) * 4;
    const float* arow = g_ln + (size_t)(m0 + lrow) * HH_;
    const float* brow = pjW + (size_t)(n0 + lrow) * HH_;

    for (int k0 = 0; k0 < 1024; k0 += 16) {
        float4 av = *(const float4*)(arow + k0 + lk4);
        *(float4*)&As[lrow][lk4] = av;
        float4 bv = *(const float4*)(brow + k0 + lk4);
        Bs[lk4 + 0][lrow] = bv.x; Bs[lk4 + 1][lrow] = bv.y;
        Bs[lk4 + 2][lrow] = bv.z; Bs[lk4 + 3][lrow] = bv.w;
        __syncthreads();
#pragma unroll
        for (int kk = 0; kk < 16; kk += 8) {
            wmma::fragment<wmma::matrix_b, 16, 16, 8, wmma::precision::tf32, wmma::row_major> b_frag;
            wmma::load_matrix_sync(b_frag, &Bs[kk][nw], 72);
#pragma unroll
            for (int i = 0; i < b_frag.num_elements; i++)
                b_frag.x[i] = wmma::__float_to_tf32(b_frag.x[i]);
#pragma unroll
            for (int i = 0; i < 2; i++) {
                wmma::fragment<wmma::matrix_a, 16, 16, 8, wmma::precision::tf32, wmma::row_major> a_frag;
                wmma::load_matrix_sync(a_frag, &As[mw + 16 * i][kk], 24);
#pragma unroll
                for (int e = 0; e < a_frag.num_elements; e++)
                    a_frag.x[e] = wmma::__float_to_tf32(a_frag.x[e]);
                wmma::mma_sync(c_frag[i], a_frag, b_frag, c_frag[i]);
            }
        }
        __syncthreads();
    }

    wmma::store_matrix_sync(&Cs[mw][nw], c_frag[0], 72, wmma::mem_row_major);
    wmma::store_matrix_sync(&Cs[mw + 16][nw], c_frag[1], 72, wmma::mem_row_major);
    __syncthreads();

    for (int e = tid; e < 1024; e += 256) {
        int row = e >> 4;
        int col = (e & 15) * 4;
        int nn = n0 + col;
        float4 cv = *(const float4*)&Cs[row][col];
        float4 o;
        o.x = tanhf(cv.x + pjb[nn + 0]);
        o.y = tanhf(cv.y + pjb[nn + 1]);
        o.z = tanhf(cv.z + pjb[nn + 2]);
        o.w = tanhf(cv.w + pjb[nn + 3]);
        *(float4*)(out + (size_t)(m0 + row) * HH_ + nn) = o;
    }
}

// ---------------- tail: x_len pass-through ----------------
__global__ void tail_kernel(const int* __restrict__ xlen, float* __restrict__ out) {
    int t = threadIdx.x;
    if (t < B_) out[(size_t)B_ * T_ * HH_ + t] = (float)xlen[t];
}

extern "C" void kernel_launch(void* const* d_in, const int* in_sizes, int n_in,
                              void* d_out, int out_size) {
    const float* x   = (const float*)d_in[0];
    const int*   xl  = (const int*)  d_in[1];
    const float* Wz  = (const float*)d_in[2];
    const float* bz  = (const float*)d_in[3];
    const float* Wh  = (const float*)d_in[4];
    const float* bh  = (const float*)d_in[5];
    const float* U   = (const float*)d_in[6];
    const float* zg  = (const float*)d_in[7];
    const float* zb  = (const float*)d_in[8];
    const float* zm  = (const float*)d_in[9];
    const float* zv  = (const float*)d_in[10];
    const float* hg  = (const float*)d_in[11];
    const float* hb  = (const float*)d_in[12];
    const float* hm  = (const float*)d_in[13];
    const float* hv  = (const float*)d_in[14];
    const float* lng = (const float*)d_in[15];
    const float* lnb = (const float*)d_in[16];
    const float* pjW = (const float*)d_in[17];
    const float* pjb = (const float*)d_in[18];
    float* out = (float*)d_out;

    prep_kernel<<<1, 1024>>>(bz, bh, zg, zb, zm, zv, hg, hb, hm, hv);
    gemm_wzh<<<dim3(16, 500), 256>>>(x, Wz, Wh);
    dummy_kernel<<<1, 32>>>();            // keeps ncu capture on scan_kernel
    scan_kernel<<<128, 512>>>(U);
    ln_kernel<<<16000, 256>>>(lng, lnb);
    gemm_proj<<<dim3(16, 250), 256>>>(pjW, pjb, out);
    if (out_size >= B_ * T_ * HH_ + B_) {
        tail_kernel<<<1, 32>>>(xl, out);
    }
    (void)in_sizes; (void)n_in;
}

// round 10
// speedup vs baseline: 2.6222x; 1.1165x over previous
#include <cuda_runtime.h>
#include <math.h>
#include <stdint.h>
#include <mma.h>

using namespace nvcuda;

// Problem constants (fixed shapes)
#define B_  16
#define T_  1000
#define TT_ 2000
#define F_  512
#define H_  512
#define HH_ 1024

// ---------------- device scratch ----------------
__device__ float g_wzh [B_ * TT_ * HH_];
__device__ float g_hseq[B_ * TT_ * H_ ];
__device__ float g_ln  [B_ * T_  * HH_];
__device__ float g_scale[HH_];
__device__ float g_bias [HH_];
__device__ __align__(16) unsigned long long g_mail[2][8][1024];

// ---------------- packed fp32x2 FMA ----------------
__device__ __forceinline__ float2 ffma2(float2 a, float2 b, float2 c) {
    float2 d;
    asm("fma.rn.f32x2 %0, %1, %2, %3;"
        : "=l"(reinterpret_cast<unsigned long long &>(d))
        : "l"(reinterpret_cast<unsigned long long &>(a)),
          "l"(reinterpret_cast<unsigned long long &>(b)),
          "l"(reinterpret_cast<unsigned long long &>(c)));
    return d;
}

__device__ __forceinline__ float4 tf32x4(float4 v) {
    v.x = wmma::__float_to_tf32(v.x);
    v.y = wmma::__float_to_tf32(v.y);
    v.z = wmma::__float_to_tf32(v.z);
    v.w = wmma::__float_to_tf32(v.w);
    return v;
}

// ---------------- prep ----------------
__global__ void prep_kernel(const float* __restrict__ bz, const float* __restrict__ bh,
                            const float* __restrict__ zg, const float* __restrict__ zb,
                            const float* __restrict__ zm, const float* __restrict__ zv,
                            const float* __restrict__ hg, const float* __restrict__ hb,
                            const float* __restrict__ hm, const float* __restrict__ hv) {
    int n = threadIdx.x;  // 1024 threads
    float sc, bi;
    if (n < 512) {
        sc = zg[n] * rsqrtf(zv[n] + 1e-5f);
        bi = (bz[n] - zm[n]) * sc + zb[n];
    } else {
        int j = n - 512;
        sc = hg[j] * rsqrtf(hv[j] + 1e-5f);
        bi = (bh[j] - hm[j]) * sc + hb[j];
    }
    g_scale[n] = sc;
    g_bias[n]  = bi;
    unsigned long long* mp = &g_mail[0][0][0];
    for (int i = n; i < 2 * 8 * 1024; i += 1024) mp[i] = 0ull;
}

__global__ void dummy_kernel() {}

// ================= tiled tf32 GEMM core (shared by both GEMMs) =================
// Block 128x64, 256 threads, warps 4m x 2n, warp tile 32x32, K-stage 16, dbuf.
// smem (aliased): As[2][128][20] (20480B) | Bs[2][64][20] (10240B) ; Cs[128][72] (36864B)
#define GEMM_SMEM_BYTES 36864

struct GemmSmem {
    // aliased storage
    char raw[GEMM_SMEM_BYTES];
    __device__ __forceinline__ float* As(int st) { return (float*)raw + st * 128 * 20; }
    __device__ __forceinline__ float* Bs(int st) { return (float*)raw + 2 * 128 * 20 + st * 64 * 20; }
    __device__ __forceinline__ float* Cs()       { return (float*)raw; }
};

// The compute body: arow/brow are per-thread row pointers (A row = m0 + (tid>>1),
// B row = n0 + (tid>>2)); K = total depth. c_frag[2][2] accumulated.
#define GEMM_BODY(K)                                                                     \
    int a_r  = tid >> 1;              /* A row 0..127 */                                 \
    int a_k  = (tid & 1) * 8;         /* 0 or 8; thread loads k4 = a_k, a_k+4 */         \
    int b_r  = tid >> 2;              /* B row (n) 0..63 */                              \
    int b_k  = (tid & 3) * 4;                                                            \
    int mw = (wid & 3) * 32;                                                             \
    int nw = (wid >> 2) * 32;                                                            \
    wmma::fragment<wmma::accumulator, 16, 16, 8, float> c_frag[2][2];                    \
    c_frag[0][0].x[0] = 0.f; /* placate compiler */                                      \
    wmma::fill_fragment(c_frag[0][0], 0.f); wmma::fill_fragment(c_frag[0][1], 0.f);      \
    wmma::fill_fragment(c_frag[1][0], 0.f); wmma::fill_fragment(c_frag[1][1], 0.f);      \
    float4 pa0 = tf32x4(*(const float4*)(arow + a_k));                                   \
    float4 pa1 = tf32x4(*(const float4*)(arow + a_k + 4));                               \
    float4 pb  = tf32x4(*(const float4*)(brow + b_k));                                   \
    *(float4*)(sm.As(0) + a_r * 20 + a_k)     = pa0;                                     \
    *(float4*)(sm.As(0) + a_r * 20 + a_k + 4) = pa1;                                     \
    *(float4*)(sm.Bs(0) + b_r * 20 + b_k)     = pb;                                      \
    __syncthreads();                                                                     \
    const int S = (K) / 16;                                                              \
    for (int s = 0; s < S; s++) {                                                        \
        int cur = s & 1;                                                                 \
        if (s + 1 < S) {                                                                 \
            int k0 = (s + 1) * 16;                                                       \
            pa0 = *(const float4*)(arow + k0 + a_k);                                     \
            pa1 = *(const float4*)(arow + k0 + a_k + 4);                                 \
            pb  = *(const float4*)(brow + k0 + b_k);                                     \
        }                                                                                \
        _Pragma("unroll")                                                                \
        for (int kk = 0; kk < 16; kk += 8) {                                             \
            wmma::fragment<wmma::matrix_b, 16, 16, 8, wmma::precision::tf32,             \
                           wmma::col_major> b_frag[2];                                   \
            wmma::load_matrix_sync(b_frag[0], sm.Bs(cur) + (nw +  0) * 20 + kk, 20);     \
            wmma::load_matrix_sync(b_frag[1], sm.Bs(cur) + (nw + 16) * 20 + kk, 20);     \
            _Pragma("unroll")                                                            \
            for (int mi = 0; mi < 2; mi++) {                                             \
                wmma::fragment<wmma::matrix_a, 16, 16, 8, wmma::precision::tf32,         \
                               wmma::row_major> a_frag;                                  \
                wmma::load_matrix_sync(a_frag, sm.As(cur) + (mw + 16 * mi) * 20 + kk, 20);\
                wmma::mma_sync(c_frag[mi][0], a_frag, b_frag[0], c_frag[mi][0]);         \
                wmma::mma_sync(c_frag[mi][1], a_frag, b_frag[1], c_frag[mi][1]);         \
            }                                                                            \
        }                                                                                \
        if (s + 1 < S) {                                                                 \
            int nxt = cur ^ 1;                                                           \
            pa0 = tf32x4(pa0); pa1 = tf32x4(pa1); pb = tf32x4(pb);                       \
            *(float4*)(sm.As(nxt) + a_r * 20 + a_k)     = pa0;                           \
            *(float4*)(sm.As(nxt) + a_r * 20 + a_k + 4) = pa1;                           \
            *(float4*)(sm.Bs(nxt) + b_r * 20 + b_k)     = pb;                            \
        }                                                                                \
        __syncthreads();                                                                 \
    }                                                                                    \
    /* dump accumulators into aliased C tile */                                          \
    wmma::store_matrix_sync(sm.Cs() + (mw +  0) * 72 + nw,      c_frag[0][0], 72, wmma::mem_row_major); \
    wmma::store_matrix_sync(sm.Cs() + (mw +  0) * 72 + nw + 16, c_frag[0][1], 72, wmma::mem_row_major); \
    wmma::store_matrix_sync(sm.Cs() + (mw + 16) * 72 + nw,      c_frag[1][0], 72, wmma::mem_row_major); \
    wmma::store_matrix_sync(sm.Cs() + (mw + 16) * 72 + nw + 16, c_frag[1][1], 72, wmma::mem_row_major); \
    __syncthreads();

// ---------------- phase 1: wzh = BN(x_cat @ [Wz;Wh]^T + b), tf32 wmma ----------------
__global__ __launch_bounds__(256) void gemm_wzh(const float* __restrict__ x,
                                                const float* __restrict__ Wz,
                                                const float* __restrict__ Wh) {
    __shared__ __align__(16) GemmSmem sm;
    int tid = threadIdx.x;
    int wid = tid >> 5;
    int m0 = blockIdx.y * 128, n0 = blockIdx.x * 64;

    // A row pointer (x_cat gather with batch reversal)
    int m = m0 + (tid >> 1);
    int b = m / TT_;
    int tp = m - b * TT_;
    const float* arow = (tp < T_) ? (x + ((size_t)(b * T_ + tp) << 9))
                                  : (x + ((size_t)((15 - b) * T_ + (tp - T_)) << 9));
    int n = n0 + (tid >> 2);
    const float* brow = (n < 512) ? (Wz + ((size_t)n << 9))
                                  : (Wh + ((size_t)(n - 512) << 9));

    GEMM_BODY(512)

    // epilogue: BN scale/bias (128x64 tile = 2048 float4s)
    for (int e = tid; e < 2048; e += 256) {
        int row = e >> 4;
        int col = (e & 15) * 4;
        int nn = n0 + col;
        float4 cv = *(const float4*)(sm.Cs() + row * 72 + col);
        float4 o;
        o.x = cv.x * g_scale[nn + 0] + g_bias[nn + 0];
        o.y = cv.y * g_scale[nn + 1] + g_bias[nn + 1];
        o.z = cv.z * g_scale[nn + 2] + g_bias[nn + 2];
        o.w = cv.w * g_scale[nn + 3] + g_bias[nn + 3];
        *(float4*)(g_wzh + (size_t)(m0 + row) * HH_ + nn) = o;
    }
}

// ---------------- phase 2: persistent scan (unchanged, proven) ----------------
__global__ __launch_bounds__(512, 1) void scan_kernel(const float* __restrict__ U) {
    __shared__ __align__(16) float h_sm[2][512];
    __shared__ float red[2][2][8][64];

    int t   = threadIdx.x;
    int grp = blockIdx.x >> 4;
    int ci  = blockIdx.x & 15;
    int b0  = grp * 2;

    int r = t & 63;
    int c = t >> 6;
    int urow = (r < 32) ? (ci * 32 + r) : (512 + ci * 32 + (r - 32));

    const float2* Up = (const float2*)(U + (size_t)urow * 512 + c * 64);
    float2 Ureg[32];
#pragma unroll
    for (int q = 0; q < 32; q++) Ureg[q] = __ldg(&Up[q]);

    for (int idx = t; idx < 1024; idx += 512) ((float*)h_sm)[idx] = 0.f;

    int bb = t >> 5, j = t & 31;
    int bcur = b0 + bb;
    int cz = ci * 32 + j, ch = 512 + ci * 32 + j;
    float nz = 0.f, nh = 0.f;
    float hp = 0.f;
    if (t < 64) {
        nz = __ldg(&g_wzh[(size_t)bcur * TT_ * HH_ + cz]);
        nh = __ldg(&g_wzh[(size_t)bcur * TT_ * HH_ + ch]);
    }
    int ds    = c * 128 + 2 * (t & 63);
    int dbb   = (ds >> 5) & 1;
    int hbase = ((ds >> 6) << 5) | (ds & 31);
    __syncthreads();

    for (int s = 0; s < TT_; s++) {
        int par2 = s & 1;
        float2 a0 = make_float2(0.f, 0.f), a1 = make_float2(0.f, 0.f);
        {
            const float4* h0 = (const float4*)&h_sm[0][c * 64];
            const float4* h1 = (const float4*)&h_sm[1][c * 64];
#pragma unroll
            for (int q = 0; q < 16; q++) {
                float4 v0 = h0[q];
                float4 v1 = h1[q];
                a0 = ffma2(Ureg[2 * q],     make_float2(v0.x, v0.y), a0);
                a0 = ffma2(Ureg[2 * q + 1], make_float2(v0.z, v0.w), a0);
                a1 = ffma2(Ureg[2 * q],     make_float2(v1.x, v1.y), a1);
                a1 = ffma2(Ureg[2 * q + 1], make_float2(v1.z, v1.w), a1);
            }
        }
        red[par2][0][c][r] = a0.x + a0.y;
        red[par2][1][c][r] = a1.x + a1.y;
        __syncthreads();

        unsigned tag = (unsigned)(s + 1);
        int par = (s + 1) & 1;

        if (t < 64) {
            float uz = 0.f, uh = 0.f;
#pragma unroll
            for (int cc = 0; cc < 8; cc++) {
                uz += red[par2][bb][cc][j];
                uh += red[par2][bb][cc][32 + j];
            }
            float zt = __fdividef(1.f, 1.f + __expf(-(nz + uz)));
            float hc = fmaxf(nh + uh, 0.f);
            float hn = zt * hp + (1.f - zt) * hc;
            hp = hn;
            __stcg(&g_hseq[((size_t)bcur * TT_ + s) * H_ + ci * 32 + j], hn);
            if (s + 1 < TT_) {
                unsigned long long pkt =
                    ((unsigned long long)tag << 32) | (unsigned long long)__float_as_uint(hn);
                asm volatile("st.relaxed.gpu.u64 [%0], %1;"
                             :: "l"(&g_mail[par][grp][ci * 64 + t]), "l"(pkt) : "memory");
                nz = __ldg(&g_wzh[((size_t)bcur * TT_ + s + 1) * HH_ + cz]);
                nh = __ldg(&g_wzh[((size_t)bcur * TT_ + s + 1) * HH_ + ch]);
            }
        }

        if (s + 1 < TT_) {
            const unsigned long long* p = &g_mail[par][grp][ds];
            unsigned long long v0, v1;
            do {
                asm volatile("ld.relaxed.gpu.v2.u64 {%0, %1}, [%2];"
                             : "=l"(v0), "=l"(v1) : "l"(p) : "memory");
            } while (((unsigned)(v0 >> 32) < tag) || ((unsigned)(v1 >> 32) < tag));
            h_sm[dbb][hbase]     = __uint_as_float((unsigned)v0);
            h_sm[dbb][hbase + 1] = __uint_as_float((unsigned)v1);
            asm volatile("bar.sync %0, %1;" :: "r"(c + 1), "r"(64) : "memory");
        }
    }
}

// ---------------- phase 3: LayerNorm (unchanged) ----------------
__global__ __launch_bounds__(256) void ln_kernel(const float* __restrict__ lng,
                                                 const float* __restrict__ lnb) {
    __shared__ float s_sum[8], s_sq[8];
    int row = blockIdx.x;
    int b = row / T_, tt = row - b * T_;
    int tid = threadIdx.x;
    int d = tid * 4;
    const float* base = (d < 512)
        ? (g_hseq + ((size_t)b * TT_ + tt) * H_ + d)
        : (g_hseq + ((size_t)(15 - b) * TT_ + T_ + tt) * H_ + (d - 512));
    float4 v = *(const float4*)base;
    float s = v.x + v.y + v.z + v.w;
    float q = v.x * v.x + v.y * v.y + v.z * v.z + v.w * v.w;
#pragma unroll
    for (int o = 16; o > 0; o >>= 1) {
        s += __shfl_down_sync(0xffffffffu, s, o);
        q += __shfl_down_sync(0xffffffffu, q, o);
    }
    int wid = tid >> 5, lid = tid & 31;
    if (lid == 0) { s_sum[wid] = s; s_sq[wid] = q; }
    __syncthreads();
    if (tid == 0) {
        float S = 0.f, Q = 0.f;
#pragma unroll
        for (int w = 0; w < 8; w++) { S += s_sum[w]; Q += s_sq[w]; }
        s_sum[0] = S; s_sq[0] = Q;
    }
    __syncthreads();
    float mu  = s_sum[0] * (1.f / 1024.f);
    float var = s_sq[0] * (1.f / 1024.f) - mu * mu;
    float inv = rsqrtf(var + 1e-5f);
    float4 g4 = *(const float4*)(lng + d);
    float4 b4 = *(const float4*)(lnb + d);
    float4 o;
    o.x = (v.x - mu) * inv * g4.x + b4.x;
    o.y = (v.y - mu) * inv * g4.y + b4.y;
    o.z = (v.z - mu) * inv * g4.z + b4.z;
    o.w = (v.w - mu) * inv * g4.w + b4.w;
    *(float4*)(g_ln + (size_t)row * HH_ + d) = o;
}

// ---------------- phase 4: out = tanh(ln @ pj_W^T + pj_b), tf32 wmma ----------------
__global__ __launch_bounds__(256) void gemm_proj(const float* __restrict__ pjW,
                                                 const float* __restrict__ pjb,
                                                 float* __restrict__ out) {
    __shared__ __align__(16) GemmSmem sm;
    int tid = threadIdx.x;
    int wid = tid >> 5;
    int m0 = blockIdx.y * 128, n0 = blockIdx.x * 64;

    const float* arow = g_ln + (size_t)(m0 + (tid >> 1)) * HH_;
    const float* brow = pjW + (size_t)(n0 + (tid >> 2)) * HH_;

    GEMM_BODY(1024)

    for (int e = tid; e < 2048; e += 256) {
        int row = e >> 4;
        int col = (e & 15) * 4;
        int nn = n0 + col;
        float4 cv = *(const float4*)(sm.Cs() + row * 72 + col);
        float4 o;
        o.x = tanhf(cv.x + pjb[nn + 0]);
        o.y = tanhf(cv.y + pjb[nn + 1]);
        o.z = tanhf(cv.z + pjb[nn + 2]);
        o.w = tanhf(cv.w + pjb[nn + 3]);
        *(float4*)(out + (size_t)(m0 + row) * HH_ + nn) = o;
    }
}

// ---------------- tail: x_len pass-through ----------------
__global__ void tail_kernel(const int* __restrict__ xlen, float* __restrict__ out) {
    int t = threadIdx.x;
    if (t < B_) out[(size_t)B_ * T_ * HH_ + t] = (float)xlen[t];
}

extern "C" void kernel_launch(void* const* d_in, const int* in_sizes, int n_in,
                              void* d_out, int out_size) {
    const float* x   = (const float*)d_in[0];
    const int*   xl  = (const int*)  d_in[1];
    const float* Wz  = (const float*)d_in[2];
    const float* bz  = (const float*)d_in[3];
    const float* Wh  = (const float*)d_in[4];
    const float* bh  = (const float*)d_in[5];
    const float* U   = (const float*)d_in[6];
    const float* zg  = (const float*)d_in[7];
    const float* zb  = (const float*)d_in[8];
    const float* zm  = (const float*)d_in[9];
    const float* zv  = (const float*)d_in[10];
    const float* hg  = (const float*)d_in[11];
    const float* hb  = (const float*)d_in[12];
    const float* hm  = (const float*)d_in[13];
    const float* hv  = (const float*)d_in[14];
    const float* lng = (const float*)d_in[15];
    const float* lnb = (const float*)d_in[16];
    const float* pjW = (const float*)d_in[17];
    const float* pjb = (const float*)d_in[18];
    float* out = (float*)d_out;

    prep_kernel<<<1, 1024>>>(bz, bh, zg, zb, zm, zv, hg, hb, hm, hv);
    gemm_wzh<<<dim3(16, 250), 256>>>(x, Wz, Wh);
    dummy_kernel<<<1, 32>>>();            // keeps ncu capture on scan_kernel
    scan_kernel<<<128, 512>>>(U);
    ln_kernel<<<16000, 256>>>(lng, lnb);
    gemm_proj<<<dim3(16, 125), 256>>>(pjW, pjb, out);
    if (out_size >= B_ * T_ * HH_ + B_) {
        tail_kernel<<<1, 32>>>(xl, out);
    }
    (void)in_sizes; (void)n_in;
}